// round 11
// baseline (speedup 1.0000x reference)
#include <cuda_runtime.h>
#include <cuda_bf16.h>
#include <cstdint>

// Problem constants
#define BB 8
#define NN 2048
#define CC 128
#define NPTS (BB*NN)        // 16384
#define KQ 12               // per-lane KNN queue depth (registers)
#define NCOLS 640           // e0|m0|e1|m1|h2pre
#define BIGF 3.402823466e38f

// gemm smem (R7-proven M128 layout): A 128x128 bf16 hi/lo, B ring of 5 chunks
#define LDSR 272
#define AH_OFF 0
#define AL_OFF 34816
#define RING_OFF 69632
#define SLOT_SZ 8704
#define SMEM_DYN (RING_OFF + 5 * SLOT_SZ)   // 113152

// ---------------- scratch (no allocations allowed) ----------------
__device__ __nv_bfloat16 g_B0hi[5 * 16384];
__device__ __nv_bfloat16 g_B0lo[5 * 16384];
__device__ __nv_bfloat16 g_B1hi[16384];
__device__ __nv_bfloat16 g_B1lo[16384];
__device__ float g_Wp3[5 * 3 * 128];
__device__ float g_P  [(size_t)NPTS * NCOLS];
__device__ int   g_nbr[NPTS * 32];
__device__ float g_H  [NPTS * CC];
__device__ float g_T1 [NPTS * CC];

// ---------------- weight packing (split-bf16, [K][N] row-major) ----------------
__global__ void pack_Bt(const float* __restrict__ W_lin, const float* __restrict__ W_src,
                        const float* __restrict__ Wg, const float* __restrict__ W1) {
    int t = blockIdx.x * blockDim.x + threadIdx.x;
    if (t >= 6 * 16384) return;
    int tile = t >> 14, idx = t & 16383;
    float w;
    if (tile < 4) {
        int li = tile >> 1;
        w = (tile & 1) ? W_lin[li * 16384 + idx] : W_src[li * 16384 + idx];
    } else if (tile == 4) {
        w = Wg[idx];
    } else {
        w = W1[idx];
    }
    __nv_bfloat16 hi = __float2bfloat16(w);
    __nv_bfloat16 lo = __float2bfloat16(w - __bfloat162float(hi));
    if (tile < 5) { g_B0hi[tile * 16384 + idx] = hi; g_B0lo[tile * 16384 + idx] = lo; }
    else          { g_B1hi[idx] = hi; g_B1lo[idx] = lo; }
}

__global__ void pack_Wp3(const float* __restrict__ W_pos, const float* __restrict__ Wg) {
    int t = blockIdx.x * blockDim.x + threadIdx.x;
    if (t >= 5 * 384) return;
    int cg = t / 384, i = t - cg * 384;
    int td = i >> 7, c = i & 127;
    float v;
    if (cg < 4) {
        int li = cg >> 1;
        float wp = W_pos[li * 384 + td * 128 + c];
        v = (cg & 1) ? -wp : wp;
    } else {
        v = Wg[(128 + td) * 128 + c];
    }
    g_Wp3[t] = v;
}

// ---------------- mma / async helpers ----------------
__device__ __forceinline__ uint32_t smem_u32(const void* p) {
    uint32_t a;
    asm("{ .reg .u64 t; cvta.to.shared.u64 t, %1; cvt.u32.u64 %0, t; }" : "=r"(a) : "l"(p));
    return a;
}
__device__ __forceinline__ void cpa16(uint32_t d, const void* s) {
    uint64_t g;
    asm("cvta.to.global.u64 %0, %1;" : "=l"(g) : "l"(s));
    asm volatile("cp.async.cg.shared.global [%0], [%1], 16;" :: "r"(d), "l"(g));
}
#define CP_COMMIT() asm volatile("cp.async.commit_group;" ::: "memory")
#define CP_WAIT3()  asm volatile("cp.async.wait_group 3;" ::: "memory")
__device__ __forceinline__ void ldsm_x4(uint32_t r[4], uint32_t a) {
    asm volatile("ldmatrix.sync.aligned.m8n8.x4.shared.b16 {%0,%1,%2,%3}, [%4];"
        : "=r"(r[0]), "=r"(r[1]), "=r"(r[2]), "=r"(r[3]) : "r"(a));
}
__device__ __forceinline__ void ldsm_x2t(uint32_t r[2], uint32_t a) {
    asm volatile("ldmatrix.sync.aligned.m8n8.x2.trans.shared.b16 {%0,%1}, [%2];"
        : "=r"(r[0]), "=r"(r[1]) : "r"(a));
}
__device__ __forceinline__ void mma_bf(float d[4], const uint32_t a[4], const uint32_t b[2]) {
    asm volatile("mma.sync.aligned.m16n8k16.row.col.f32.bf16.bf16.f32 "
        "{%0,%1,%2,%3}, {%4,%5,%6,%7}, {%8,%9}, {%0,%1,%2,%3};"
        : "+f"(d[0]), "+f"(d[1]), "+f"(d[2]), "+f"(d[3])
        : "r"(a[0]), "r"(a[1]), "r"(a[2]), "r"(a[3]), "r"(b[0]), "r"(b[1]));
}
__device__ __forceinline__ uint32_t bfpack(float x, float y) {
    __nv_bfloat16 hx = __float2bfloat16(x), hy = __float2bfloat16(y);
    return ((uint32_t)__bfloat16_as_ushort(hy) << 16) | __bfloat16_as_ushort(hx);
}

// ---------------- persistent-row split-bf16 GEMM (R7-proven, M-tile 128) ----------------
template<int EPI, int NCG>
__global__ __launch_bounds__(256) void gemm_p(
    const float* __restrict__ A,
    const __nv_bfloat16* __restrict__ Bhi, const __nv_bfloat16* __restrict__ Blo,
    const float* __restrict__ bias, const float* __restrict__ Wp3,
    const float* __restrict__ pos, float* __restrict__ C, int ldc)
{
    extern __shared__ char sm[];
    __shared__ float sWb[5 * 384 + 128];
    const int tid = threadIdx.x;
    const int lane = tid & 31, wid = tid >> 5;
    const int row0 = blockIdx.x * 128;
    const int NSTEP = NCG * 8;
    const uint32_t smb = smem_u32(sm);

    {
        int r = tid >> 4, c = tid & 15;
#pragma unroll
        for (int s = 0; s < 3; ++s) {
            int cg = s >> 3, ks = s & 7;
            size_t goff = ((size_t)cg * 128 + ks * 16 + r) * 128 + c * 8;
            uint32_t dst = smb + RING_OFF + s * SLOT_SZ + r * LDSR + c * 16;
            cpa16(dst, Bhi + goff);
            cpa16(dst + 4352, Blo + goff);
            CP_COMMIT();
        }
    }
    {
        int r = tid >> 1, half = tid & 1;
        const float* Ar = A + (size_t)(row0 + r) * 128 + half * 64;
        uint32_t* Ah = (uint32_t*)(sm + AH_OFF + r * LDSR + half * 128);
        uint32_t* Al = (uint32_t*)(sm + AL_OFF + r * LDSR + half * 128);
#pragma unroll
        for (int f = 0; f < 16; ++f) {
            float4 v = *(const float4*)(Ar + f * 4);
            float hx = __bfloat162float(__float2bfloat16(v.x));
            float hy = __bfloat162float(__float2bfloat16(v.y));
            float hz = __bfloat162float(__float2bfloat16(v.z));
            float hw = __bfloat162float(__float2bfloat16(v.w));
            Ah[f * 2]     = bfpack(hx, hy);
            Ah[f * 2 + 1] = bfpack(hz, hw);
            Al[f * 2]     = bfpack(v.x - hx, v.y - hy);
            Al[f * 2 + 1] = bfpack(v.z - hz, v.w - hw);
        }
    }
    if (EPI == 0)
        for (int i = tid; i < 1920; i += 256) sWb[i] = Wp3[i];
    if (tid < 128) sWb[1920 + tid] = bias[tid];

    const int wr = wid & 3, wc = wid >> 2;
    const uint32_t aA = smb + AH_OFF + (uint32_t)(wr * 32 + (lane & 15)) * LDSR
                      + ((lane >> 4) << 4);
    const uint32_t bBbase = smb + RING_OFF + (uint32_t)(lane & 15) * LDSR + wc * 128;

    float prx[2][2][3];
    if (EPI == 0) {
#pragma unroll
        for (int mt = 0; mt < 2; ++mt) {
            int r0 = row0 + wr * 32 + mt * 16 + (lane >> 2);
            prx[mt][0][0] = pos[r0 * 3];       prx[mt][0][1] = pos[r0 * 3 + 1];
            prx[mt][0][2] = pos[r0 * 3 + 2];
            prx[mt][1][0] = pos[(r0 + 8) * 3]; prx[mt][1][1] = pos[(r0 + 8) * 3 + 1];
            prx[mt][1][2] = pos[(r0 + 8) * 3 + 2];
        }
    }

    float d[2][8][4];
#pragma unroll
    for (int mt = 0; mt < 2; ++mt)
#pragma unroll
        for (int nt = 0; nt < 8; ++nt)
#pragma unroll
            for (int q = 0; q < 4; ++q) d[mt][nt][q] = 0.f;

    int slot_w = 3, slot_r = 0;
#pragma unroll 1
    for (int s = 0; s < NSTEP; ++s) {
        if (s + 3 < NSTEP) {
            int sp = s + 3;
            int cg = sp >> 3, ks = sp & 7;
            int r = tid >> 4, c = tid & 15;
            size_t goff = ((size_t)cg * 128 + ks * 16 + r) * 128 + c * 8;
            uint32_t dst = smb + RING_OFF + slot_w * SLOT_SZ + r * LDSR + c * 16;
            cpa16(dst, Bhi + goff);
            cpa16(dst + 4352, Blo + goff);
        }
        CP_COMMIT();
        CP_WAIT3();
        __syncthreads();

        const int ks = s & 7;
        uint32_t ah[2][4], al[2][4];
        uint32_t ak = aA + ks * 32;
        ldsm_x4(ah[0], ak);
        ldsm_x4(ah[1], ak + 16 * LDSR);
        ldsm_x4(al[0], ak + (AL_OFF - AH_OFF));
        ldsm_x4(al[1], ak + (AL_OFF - AH_OFF) + 16 * LDSR);
        uint32_t bk = bBbase + (uint32_t)slot_r * SLOT_SZ;
#pragma unroll
        for (int nt = 0; nt < 8; ++nt) {
            uint32_t bh[2], bl[2];
            ldsm_x2t(bh, bk + nt * 16);
            ldsm_x2t(bl, bk + nt * 16 + 4352);
            mma_bf(d[0][nt], ah[0], bh);
            mma_bf(d[0][nt], ah[0], bl);
            mma_bf(d[0][nt], al[0], bh);
            mma_bf(d[1][nt], ah[1], bh);
            mma_bf(d[1][nt], ah[1], bl);
            mma_bf(d[1][nt], al[1], bh);
        }
        slot_w = (slot_w == 4) ? 0 : slot_w + 1;
        slot_r = (slot_r == 4) ? 0 : slot_r + 1;

        if (ks == 7) {
            const int cg = s >> 3;
            const float* sW0 = sWb + cg * 384;
#pragma unroll
            for (int mt = 0; mt < 2; ++mt) {
                int r0 = row0 + wr * 32 + mt * 16 + (lane >> 2);
                int r1 = r0 + 8;
#pragma unroll
                for (int nt = 0; nt < 8; ++nt) {
                    int c = wc * 64 + nt * 8 + (lane & 3) * 2;
                    float u0 = d[mt][nt][0], u1 = d[mt][nt][1];
                    float u2 = d[mt][nt][2], u3 = d[mt][nt][3];
                    if (EPI == 0) {
                        float q0x = prx[mt][0][0], q0y = prx[mt][0][1], q0z = prx[mt][0][2];
                        float q1x = prx[mt][1][0], q1y = prx[mt][1][1], q1z = prx[mt][1][2];
                        u0 += q0x * sW0[c]       + q0y * sW0[128 + c]     + q0z * sW0[256 + c];
                        u1 += q0x * sW0[c + 1]   + q0y * sW0[128 + c + 1] + q0z * sW0[256 + c + 1];
                        u2 += q1x * sW0[c]       + q1y * sW0[128 + c]     + q1z * sW0[256 + c];
                        u3 += q1x * sW0[c + 1]   + q1y * sW0[128 + c + 1] + q1z * sW0[256 + c + 1];
                        if (cg == 4) {
                            u0 += sWb[1920 + c];     u0 = u0 > 0.f ? u0 : 0.2f * u0;
                            u1 += sWb[1920 + c + 1]; u1 = u1 > 0.f ? u1 : 0.2f * u1;
                            u2 += sWb[1920 + c];     u2 = u2 > 0.f ? u2 : 0.2f * u2;
                            u3 += sWb[1920 + c + 1]; u3 = u3 > 0.f ? u3 : 0.2f * u3;
                        } else if (!(cg & 1)) {
                            u0 = __expf(-u0); u1 = __expf(-u1);
                            u2 = __expf(-u2); u3 = __expf(-u3);
                        }
                    } else {
                        u0 += sWb[1920 + c];     u0 = u0 > 0.f ? u0 : 0.2f * u0;
                        u1 += sWb[1920 + c + 1]; u1 = u1 > 0.f ? u1 : 0.2f * u1;
                        u2 += sWb[1920 + c];     u2 = u2 > 0.f ? u2 : 0.2f * u2;
                        u3 += sWb[1920 + c + 1]; u3 = u3 > 0.f ? u3 : 0.2f * u3;
                    }
                    *(float2*)(C + (size_t)r0 * ldc + cg * 128 + c) = make_float2(u0, u1);
                    *(float2*)(C + (size_t)r1 * ldc + cg * 128 + c) = make_float2(u2, u3);
                    d[mt][nt][0] = 0.f; d[mt][nt][1] = 0.f;
                    d[mt][nt][2] = 0.f; d[mt][nt][3] = 0.f;
                }
            }
        }
    }
}

// ---------------- KNN: rank-based parallel insert, 8 queries / 256-thread block ---------
__global__ __launch_bounds__(256) void knn_kernel(const float* __restrict__ pos) {
    __shared__ float4 p4[NN];            // 32 KB
    __shared__ float qd[8][KQ][32];      // 12 KB
    __shared__ int   qi[8][KQ][32];      // 12 KB
    int tid = threadIdx.x;
    int b = blockIdx.x >> 8;             // 256 blocks per batch, 8 queries each
    int grp = blockIdx.x & 255;
    const float* pb = pos + (size_t)b * NN * 3;
    for (int j = tid; j < NN; j += 256) {
        float X = pb[j * 3], Y = pb[j * 3 + 1], Z = pb[j * 3 + 2];
        p4[j] = make_float4(X, Y, Z, X * X + Y * Y + Z * Z);
    }
    __syncthreads();
    int wid = tid >> 5, lane = tid & 31;
    int il = grp * 8 + wid;
    float4 q = p4[il];

    float qdr[KQ]; int qir[KQ];
#pragma unroll
    for (int p = 0; p < KQ; ++p) { qdr[p] = BIGF; qir[p] = 0x7fffffff; }

#pragma unroll 2
    for (int t = 0; t < NN / 32; ++t) {
        int j = lane + (t << 5);
        float4 pj = p4[j];
        float d2 = q.w + pj.w - 2.f * (q.x * pj.x + q.y * pj.y + q.z * pj.z);
        if (j != il && d2 < qdr[KQ - 1]) {
            // rank = count of entries <= d2  (ties: new goes AFTER equals, matching
            // the shift-chain semantics; per-lane idx increases with t)
            int rank = 0;
#pragma unroll
            for (int p = 0; p < KQ; ++p) rank += (qdr[p] <= d2) ? 1 : 0;
            // parallel shift+place: all positions independent (no serial carry)
#pragma unroll
            for (int p = KQ - 1; p >= 1; --p) {
                float nv = (p > rank) ? qdr[p - 1] : ((p == rank) ? d2 : qdr[p]);
                int   ni = (p > rank) ? qir[p - 1] : ((p == rank) ? j  : qir[p]);
                qdr[p] = nv; qir[p] = ni;
            }
            if (rank == 0) { qdr[0] = d2; qir[0] = j; }
        }
    }
#pragma unroll
    for (int p = 0; p < KQ; ++p) { qd[wid][p][lane] = qdr[p]; qi[wid][p][lane] = qir[p]; }
    __syncwarp();

    // lexicographic 32-way merge of per-lane sorted queues
    int ptr = 0;
    float head = qdr[0]; int hidx = qir[0];
    int outj = 0;
    float lastd = 0.f; int lasti = 0;
    for (int r = 0; r < 32; ++r) {
        float bd = head; int bi = hidx; int bl = lane;
#pragma unroll
        for (int o = 16; o; o >>= 1) {
            float od = __shfl_xor_sync(0xffffffffu, bd, o);
            int oi = __shfl_xor_sync(0xffffffffu, bi, o);
            int ol = __shfl_xor_sync(0xffffffffu, bl, o);
            if (od < bd || (od == bd && oi < bi)) { bd = od; bi = oi; bl = ol; }
        }
        if (lane == r) outj = bi;
        if (lane == bl) {
            ++ptr;
            if (ptr < KQ) { head = qd[wid][ptr][lane]; hidx = qi[wid][ptr][lane]; }
            else          { head = BIGF; hidx = 0x7fffffff; }
        }
        lastd = bd; lasti = bi;
    }
    float lmd = qdr[KQ - 1]; int lmi = qir[KQ - 1];
    bool unsafe = (lmd < lastd) || (lmd == lastd && lmi < lasti);
    if (__ballot_sync(0xffffffffu, unsafe)) {
        // exact fallback (rare): repeated lexicographic min > previous
        float pd = -BIGF; int pi = -1;
        for (int r = 0; r < 32; ++r) {
            float bd = BIGF; int bi = 0x7fffffff;
            for (int t = 0; t < NN / 32; ++t) {
                int j = lane + (t << 5);
                float4 pj = p4[j];
                float d2 = q.w + pj.w - 2.f * (q.x * pj.x + q.y * pj.y + q.z * pj.z);
                if (j == il) d2 += 1e10f;
                bool gt = (d2 > pd) || (d2 == pd && j > pi);
                if (gt && (d2 < bd || (d2 == bd && j < bi))) { bd = d2; bi = j; }
            }
#pragma unroll
            for (int o = 16; o; o >>= 1) {
                float od = __shfl_xor_sync(0xffffffffu, bd, o);
                int oi = __shfl_xor_sync(0xffffffffu, bi, o);
                if (od < bd || (od == bd && oi < bi)) { bd = od; bi = oi; }
            }
            if (lane == r) outj = bi;
            pd = bd; pi = bi;
        }
    }
    g_nbr[((size_t)b * NN + il) * 32 + lane] = b * NN + outj;
}

// ---------------- neighborhood aggregation (both dilations fused) ----------------
__global__ __launch_bounds__(128) void aggregate_kernel(
    const float* __restrict__ pos, const float* __restrict__ W_pos,
    const float* __restrict__ b_pos)
{
    __shared__ float sWp[3][128];
    __shared__ float sbp[128];
    int tid = threadIdx.x;
    sbp[tid] = b_pos[tid] + b_pos[128 + tid];
#pragma unroll
    for (int r = 0; r < 3; ++r)
        sWp[r][tid] = W_pos[r * 128 + tid] + W_pos[384 + r * 128 + tid];
    __syncthreads();

    int w = tid >> 5, lane = tid & 31;
    int i = blockIdx.x * 4 + w;
    int myn = g_nbr[(size_t)i * 32 + lane];
    int c = lane << 2;

    float4 a0 = {0,0,0,0}, s0 = {0,0,0,0};
#pragma unroll
    for (int k = 0; k <= 16; ++k) {
        int j = (k < 16) ? __shfl_sync(0xffffffffu, myn, k) : i;
        const float* pr = g_P + (size_t)j * NCOLS + c;
        float4 e = *(const float4*)pr;
        float4 m = *(const float4*)(pr + 128);
        s0.x += e.x; s0.y += e.y; s0.z += e.z; s0.w += e.w;
        a0.x += e.x * m.x; a0.y += e.y * m.y; a0.z += e.z * m.z; a0.w += e.w * m.w;
    }
    float4 a1 = {0,0,0,0}, s1 = {0,0,0,0};
#pragma unroll
    for (int k = 0; k <= 16; ++k) {
        int j = (k < 16) ? __shfl_sync(0xffffffffu, myn, 2 * k) : i;
        const float* pr = g_P + (size_t)j * NCOLS + 256 + c;
        float4 e = *(const float4*)pr;
        float4 m = *(const float4*)(pr + 128);
        s1.x += e.x; s1.y += e.y; s1.z += e.z; s1.w += e.w;
        a1.x += e.x * m.x; a1.y += e.y * m.y; a1.z += e.z * m.z; a1.w += e.w * m.w;
    }

    const float* pri = g_P + (size_t)i * NCOLS;
    float4 h2 = *(const float4*)(pri + 512 + c);
    float pix = pos[i * 3], piy = pos[i * 3 + 1], piz = pos[i * 3 + 2];
    float4 outv;
    outv.x = h2.x + a0.x / s0.x + a1.x / s1.x + sbp[c + 0]
           + pix * sWp[0][c + 0] + piy * sWp[1][c + 0] + piz * sWp[2][c + 0];
    outv.y = h2.y + a0.y / s0.y + a1.y / s1.y + sbp[c + 1]
           + pix * sWp[0][c + 1] + piy * sWp[1][c + 1] + piz * sWp[2][c + 1];
    outv.z = h2.z + a0.z / s0.z + a1.z / s1.z + sbp[c + 2]
           + pix * sWp[0][c + 2] + piy * sWp[1][c + 2] + piz * sWp[2][c + 2];
    outv.w = h2.w + a0.w / s0.w + a1.w / s1.w + sbp[c + 3]
           + pix * sWp[0][c + 3] + piy * sWp[1][c + 3] + piz * sWp[2][c + 3];
    *(float4*)(g_H + (size_t)i * CC + c) = outv;
}

// ---------------- final projection to 3 channels + residual pos ----------------
__global__ __launch_bounds__(128) void final_out(
    const float* __restrict__ pos, const float* __restrict__ W2,
    const float* __restrict__ b2, float* __restrict__ out)
{
    __shared__ float sW[384];
    int tid = threadIdx.x;
    for (int t = tid; t < 384; t += 128) sW[t] = W2[t];
    __syncthreads();
    int w = tid >> 5, lane = tid & 31;
    int i = blockIdx.x * 4 + w;
    const float* T = g_T1 + (size_t)i * CC;
    float a0 = 0.f, a1 = 0.f, a2 = 0.f;
    for (int c = lane; c < CC; c += 32) {
        float t = T[c];
        a0 += t * sW[c * 3 + 0];
        a1 += t * sW[c * 3 + 1];
        a2 += t * sW[c * 3 + 2];
    }
#pragma unroll
    for (int o = 16; o; o >>= 1) {
        a0 += __shfl_xor_sync(0xffffffffu, a0, o);
        a1 += __shfl_xor_sync(0xffffffffu, a1, o);
        a2 += __shfl_xor_sync(0xffffffffu, a2, o);
    }
    if (lane == 0) {
        out[i * 3 + 0] = a0 + b2[0] + pos[i * 3 + 0];
        out[i * 3 + 1] = a1 + b2[1] + pos[i * 3 + 1];
        out[i * 3 + 2] = a2 + b2[2] + pos[i * 3 + 2];
    }
}

// ---------------- launcher ----------------
extern "C" void kernel_launch(void* const* d_in, const int* in_sizes, int n_in,
                              void* d_out, int out_size) {
    const float* x     = (const float*)d_in[0];
    const float* pos   = (const float*)d_in[1];
    const float* W_lin = (const float*)d_in[2];
    const float* W_src = (const float*)d_in[3];
    // d_in[4] = W_dst: cancels in the per-channel softmax, unused
    const float* W_pos = (const float*)d_in[5];
    const float* b_pos = (const float*)d_in[6];
    const float* Wg    = (const float*)d_in[7];
    const float* bg    = (const float*)d_in[8];
    const float* W1    = (const float*)d_in[9];
    const float* b1    = (const float*)d_in[10];
    const float* W2    = (const float*)d_in[11];
    const float* b2    = (const float*)d_in[12];
    float* out = (float*)d_out;

    cudaFuncSetAttribute(gemm_p<0,5>, cudaFuncAttributeMaxDynamicSharedMemorySize, SMEM_DYN);
    cudaFuncSetAttribute(gemm_p<1,1>, cudaFuncAttributeMaxDynamicSharedMemorySize, SMEM_DYN);

    pack_Bt<<<(6 * 16384 + 255) / 256, 256>>>(W_lin, W_src, Wg, W1);
    pack_Wp3<<<(5 * 384 + 255) / 256, 256>>>(W_pos, Wg);
    knn_kernel<<<NPTS / 8, 256>>>(pos);

    __nv_bfloat16 *B0h, *B0l, *B1h, *B1l;
    float *Wp3, *P, *H, *T1;
    cudaGetSymbolAddress((void**)&B0h, g_B0hi);
    cudaGetSymbolAddress((void**)&B0l, g_B0lo);
    cudaGetSymbolAddress((void**)&B1h, g_B1hi);
    cudaGetSymbolAddress((void**)&B1l, g_B1lo);
    cudaGetSymbolAddress((void**)&Wp3, g_Wp3);
    cudaGetSymbolAddress((void**)&P,   g_P);
    cudaGetSymbolAddress((void**)&H,   g_H);
    cudaGetSymbolAddress((void**)&T1,  g_T1);

    gemm_p<0,5><<<NPTS / 128, 256, SMEM_DYN>>>(x, B0h, B0l, bg, Wp3, pos, P, NCOLS);
    aggregate_kernel<<<NPTS / 4, 128>>>(pos, W_pos, b_pos);
    gemm_p<1,1><<<NPTS / 128, 256, SMEM_DYN>>>(H, B1h, B1l, b1, Wp3, pos, T1, CC);
    final_out<<<NPTS / 4, 128>>>(pos, W2, b2, out);
}

// round 12
// speedup vs baseline: 1.1502x; 1.1502x over previous
#include <cuda_runtime.h>
#include <cuda_bf16.h>
#include <cstdint>

// Problem constants
#define BB 8
#define NN 2048
#define CC 128
#define NPTS (BB*NN)        // 16384
#define KQ 12               // per-lane KNN queue depth (registers)
#define NCOLS 640           // e0|m0|e1|m1|h2pre
#define BIGF 3.402823466e38f

// gemm smem (R8-proven M64 layout): A tile 64x128 bf16 hi/lo, B ring of 5 chunks
#define LDSR 272
#define AH_OFF 0
#define AL_OFF 17408
#define RING_OFF 34816
#define SLOT_SZ 8704
#define SMEM_DYN (RING_OFF + 5 * SLOT_SZ)   // 78336

// ---------------- scratch (no allocations allowed) ----------------
__device__ __nv_bfloat16 g_B0hi[5 * 16384];
__device__ __nv_bfloat16 g_B0lo[5 * 16384];
__device__ __nv_bfloat16 g_B1hi[16384];
__device__ __nv_bfloat16 g_B1lo[16384];
__device__ float g_Wp3[5 * 3 * 128];
__device__ float g_P  [(size_t)NPTS * NCOLS];
__device__ int   g_nbr[NPTS * 32];
__device__ float g_H  [NPTS * CC];

// ---------------- combined weight packing (split-bf16 tiles + Wp3) ----------------
__global__ void pack_all(const float* __restrict__ W_lin, const float* __restrict__ W_src,
                         const float* __restrict__ Wg, const float* __restrict__ W1,
                         const float* __restrict__ W_pos) {
    int t = blockIdx.x * blockDim.x + threadIdx.x;
    if (t < 6 * 16384) {
        int tile = t >> 14, idx = t & 16383;
        float w;
        if (tile < 4) {
            int li = tile >> 1;
            w = (tile & 1) ? W_lin[li * 16384 + idx] : W_src[li * 16384 + idx];
        } else if (tile == 4) {
            w = Wg[idx];
        } else {
            w = W1[idx];
        }
        __nv_bfloat16 hi = __float2bfloat16(w);
        __nv_bfloat16 lo = __float2bfloat16(w - __bfloat162float(hi));
        if (tile < 5) { g_B0hi[tile * 16384 + idx] = hi; g_B0lo[tile * 16384 + idx] = lo; }
        else          { g_B1hi[idx] = hi; g_B1lo[idx] = lo; }
    } else if (t < 6 * 16384 + 5 * 384) {
        int u = t - 6 * 16384;
        int cg = u / 384, i = u - cg * 384;
        int td = i >> 7, c = i & 127;
        float v;
        if (cg < 4) {
            int li = cg >> 1;
            float wp = W_pos[li * 384 + td * 128 + c];
            v = (cg & 1) ? -wp : wp;
        } else {
            v = Wg[(128 + td) * 128 + c];
        }
        g_Wp3[u] = v;
    }
}

// ---------------- mma / async helpers ----------------
__device__ __forceinline__ uint32_t smem_u32(const void* p) {
    uint32_t a;
    asm("{ .reg .u64 t; cvta.to.shared.u64 t, %1; cvt.u32.u64 %0, t; }" : "=r"(a) : "l"(p));
    return a;
}
__device__ __forceinline__ void cpa16(uint32_t d, const void* s) {
    uint64_t g;
    asm("cvta.to.global.u64 %0, %1;" : "=l"(g) : "l"(s));
    asm volatile("cp.async.cg.shared.global [%0], [%1], 16;" :: "r"(d), "l"(g));
}
#define CP_COMMIT() asm volatile("cp.async.commit_group;" ::: "memory")
#define CP_WAIT3()  asm volatile("cp.async.wait_group 3;" ::: "memory")
__device__ __forceinline__ void ldsm_x4(uint32_t r[4], uint32_t a) {
    asm volatile("ldmatrix.sync.aligned.m8n8.x4.shared.b16 {%0,%1,%2,%3}, [%4];"
        : "=r"(r[0]), "=r"(r[1]), "=r"(r[2]), "=r"(r[3]) : "r"(a));
}
__device__ __forceinline__ void ldsm_x2t(uint32_t r[2], uint32_t a) {
    asm volatile("ldmatrix.sync.aligned.m8n8.x2.trans.shared.b16 {%0,%1}, [%2];"
        : "=r"(r[0]), "=r"(r[1]) : "r"(a));
}
__device__ __forceinline__ void mma_bf(float d[4], const uint32_t a[4], const uint32_t b[2]) {
    asm volatile("mma.sync.aligned.m16n8k16.row.col.f32.bf16.bf16.f32 "
        "{%0,%1,%2,%3}, {%4,%5,%6,%7}, {%8,%9}, {%0,%1,%2,%3};"
        : "+f"(d[0]), "+f"(d[1]), "+f"(d[2]), "+f"(d[3])
        : "r"(a[0]), "r"(a[1]), "r"(a[2]), "r"(a[3]), "r"(b[0]), "r"(b[1]));
}
__device__ __forceinline__ uint32_t bfpack(float x, float y) {
    __nv_bfloat16 hx = __float2bfloat16(x), hy = __float2bfloat16(y);
    return ((uint32_t)__bfloat16_as_ushort(hy) << 16) | __bfloat16_as_ushort(hx);
}

// ---------------- gemm0: persistent-row split-bf16, M-tile 64, 5 col groups (R8) --------
__global__ __launch_bounds__(256) void gemm_p0(
    const float* __restrict__ A,
    const __nv_bfloat16* __restrict__ Bhi, const __nv_bfloat16* __restrict__ Blo,
    const float* __restrict__ bias, const float* __restrict__ Wp3,
    const float* __restrict__ pos, float* __restrict__ C)
{
    extern __shared__ char sm[];
    __shared__ float sWb[5 * 384 + 128];
    const int tid = threadIdx.x;
    const int lane = tid & 31, wid = tid >> 5;
    const int row0 = blockIdx.x * 64;
    const int NSTEP = 5 * 8;
    const int ldc = NCOLS;
    const uint32_t smb = smem_u32(sm);

    {
        int r = tid >> 4, c = tid & 15;
#pragma unroll
        for (int s = 0; s < 3; ++s) {
            int cg = s >> 3, ks = s & 7;
            size_t goff = ((size_t)cg * 128 + ks * 16 + r) * 128 + c * 8;
            uint32_t dst = smb + RING_OFF + s * SLOT_SZ + r * LDSR + c * 16;
            cpa16(dst, Bhi + goff);
            cpa16(dst + 4352, Blo + goff);
            CP_COMMIT();
        }
    }
    {
        int r = tid >> 2, qch = tid & 3;
        const float* Ar = A + (size_t)(row0 + r) * 128 + qch * 32;
        uint32_t* Ah = (uint32_t*)(sm + AH_OFF + r * LDSR + qch * 64);
        uint32_t* Al = (uint32_t*)(sm + AL_OFF + r * LDSR + qch * 64);
#pragma unroll
        for (int f = 0; f < 8; ++f) {
            float4 v = *(const float4*)(Ar + f * 4);
            float hx = __bfloat162float(__float2bfloat16(v.x));
            float hy = __bfloat162float(__float2bfloat16(v.y));
            float hz = __bfloat162float(__float2bfloat16(v.z));
            float hw = __bfloat162float(__float2bfloat16(v.w));
            Ah[f * 2]     = bfpack(hx, hy);
            Ah[f * 2 + 1] = bfpack(hz, hw);
            Al[f * 2]     = bfpack(v.x - hx, v.y - hy);
            Al[f * 2 + 1] = bfpack(v.z - hz, v.w - hw);
        }
    }
    for (int i = tid; i < 1920; i += 256) sWb[i] = Wp3[i];
    if (tid < 128) sWb[1920 + tid] = bias[tid];

    const int wr = wid & 3, wc = wid >> 2;
    const uint32_t aA = smb + AH_OFF + (uint32_t)(wr * 16 + (lane & 15)) * LDSR
                      + ((lane >> 4) << 4);
    const uint32_t bBbase = smb + RING_OFF + (uint32_t)(lane & 15) * LDSR + wc * 128;

    float prx[2][3];
    {
        int r0 = row0 + wr * 16 + (lane >> 2);
        prx[0][0] = pos[r0 * 3];       prx[0][1] = pos[r0 * 3 + 1];
        prx[0][2] = pos[r0 * 3 + 2];
        prx[1][0] = pos[(r0 + 8) * 3]; prx[1][1] = pos[(r0 + 8) * 3 + 1];
        prx[1][2] = pos[(r0 + 8) * 3 + 2];
    }

    float d[8][4];
#pragma unroll
    for (int nt = 0; nt < 8; ++nt)
#pragma unroll
        for (int q = 0; q < 4; ++q) d[nt][q] = 0.f;

    int slot_w = 3, slot_r = 0;
#pragma unroll 1
    for (int s = 0; s < NSTEP; ++s) {
        if (s + 3 < NSTEP) {
            int sp = s + 3;
            int cg = sp >> 3, ks = sp & 7;
            int r = tid >> 4, c = tid & 15;
            size_t goff = ((size_t)cg * 128 + ks * 16 + r) * 128 + c * 8;
            uint32_t dst = smb + RING_OFF + slot_w * SLOT_SZ + r * LDSR + c * 16;
            cpa16(dst, Bhi + goff);
            cpa16(dst + 4352, Blo + goff);
        }
        CP_COMMIT();
        CP_WAIT3();
        __syncthreads();

        const int ks = s & 7;
        uint32_t ah[4], al[4];
        uint32_t ak = aA + ks * 32;
        ldsm_x4(ah, ak);
        ldsm_x4(al, ak + (AL_OFF - AH_OFF));
        uint32_t bk = bBbase + (uint32_t)slot_r * SLOT_SZ;
#pragma unroll
        for (int nt = 0; nt < 8; ++nt) {
            uint32_t bh[2], bl[2];
            ldsm_x2t(bh, bk + nt * 16);
            ldsm_x2t(bl, bk + nt * 16 + 4352);
            mma_bf(d[nt], ah, bh);
            mma_bf(d[nt], ah, bl);
            mma_bf(d[nt], al, bh);
        }
        slot_w = (slot_w == 4) ? 0 : slot_w + 1;
        slot_r = (slot_r == 4) ? 0 : slot_r + 1;

        if (ks == 7) {
            const int cg = s >> 3;
            const float* sW0 = sWb + cg * 384;
            int r0 = row0 + wr * 16 + (lane >> 2);
            int r1 = r0 + 8;
#pragma unroll
            for (int nt = 0; nt < 8; ++nt) {
                int c = wc * 64 + nt * 8 + (lane & 3) * 2;
                float u0 = d[nt][0], u1 = d[nt][1];
                float u2 = d[nt][2], u3 = d[nt][3];
                u0 += prx[0][0] * sW0[c]     + prx[0][1] * sW0[128 + c]     + prx[0][2] * sW0[256 + c];
                u1 += prx[0][0] * sW0[c + 1] + prx[0][1] * sW0[128 + c + 1] + prx[0][2] * sW0[256 + c + 1];
                u2 += prx[1][0] * sW0[c]     + prx[1][1] * sW0[128 + c]     + prx[1][2] * sW0[256 + c];
                u3 += prx[1][0] * sW0[c + 1] + prx[1][1] * sW0[128 + c + 1] + prx[1][2] * sW0[256 + c + 1];
                if (cg == 4) {
                    u0 += sWb[1920 + c];     u0 = u0 > 0.f ? u0 : 0.2f * u0;
                    u1 += sWb[1920 + c + 1]; u1 = u1 > 0.f ? u1 : 0.2f * u1;
                    u2 += sWb[1920 + c];     u2 = u2 > 0.f ? u2 : 0.2f * u2;
                    u3 += sWb[1920 + c + 1]; u3 = u3 > 0.f ? u3 : 0.2f * u3;
                } else if (!(cg & 1)) {
                    u0 = __expf(-u0); u1 = __expf(-u1);
                    u2 = __expf(-u2); u3 = __expf(-u3);
                }
                *(float2*)(C + (size_t)r0 * ldc + cg * 128 + c) = make_float2(u0, u1);
                *(float2*)(C + (size_t)r1 * ldc + cg * 128 + c) = make_float2(u2, u3);
                d[nt][0] = 0.f; d[nt][1] = 0.f; d[nt][2] = 0.f; d[nt][3] = 0.f;
            }
        }
    }
}

// ---------------- gemm1 fused with final projection: out = T1@W2 + b2 + pos ------------
__global__ __launch_bounds__(256) void gemm1_final(
    const float* __restrict__ A,
    const __nv_bfloat16* __restrict__ Bhi, const __nv_bfloat16* __restrict__ Blo,
    const float* __restrict__ bias, const float* __restrict__ W2,
    const float* __restrict__ b2, const float* __restrict__ pos,
    float* __restrict__ out)
{
    extern __shared__ char sm[];
    __shared__ float sbias[128];
    __shared__ float sW2[384];
    __shared__ float sred[64][2][3];
    const int tid = threadIdx.x;
    const int lane = tid & 31, wid = tid >> 5;
    const int row0 = blockIdx.x * 64;
    const uint32_t smb = smem_u32(sm);

    {
        int r = tid >> 4, c = tid & 15;
#pragma unroll
        for (int s = 0; s < 3; ++s) {
            size_t goff = ((size_t)s * 16 + r) * 128 + c * 8;
            uint32_t dst = smb + RING_OFF + s * SLOT_SZ + r * LDSR + c * 16;
            cpa16(dst, Bhi + goff);
            cpa16(dst + 4352, Blo + goff);
            CP_COMMIT();
        }
    }
    {
        int r = tid >> 2, qch = tid & 3;
        const float* Ar = A + (size_t)(row0 + r) * 128 + qch * 32;
        uint32_t* Ah = (uint32_t*)(sm + AH_OFF + r * LDSR + qch * 64);
        uint32_t* Al = (uint32_t*)(sm + AL_OFF + r * LDSR + qch * 64);
#pragma unroll
        for (int f = 0; f < 8; ++f) {
            float4 v = *(const float4*)(Ar + f * 4);
            float hx = __bfloat162float(__float2bfloat16(v.x));
            float hy = __bfloat162float(__float2bfloat16(v.y));
            float hz = __bfloat162float(__float2bfloat16(v.z));
            float hw = __bfloat162float(__float2bfloat16(v.w));
            Ah[f * 2]     = bfpack(hx, hy);
            Ah[f * 2 + 1] = bfpack(hz, hw);
            Al[f * 2]     = bfpack(v.x - hx, v.y - hy);
            Al[f * 2 + 1] = bfpack(v.z - hz, v.w - hw);
        }
    }
    if (tid < 128) sbias[tid] = bias[tid];
    for (int i = tid; i < 384; i += 256) sW2[i] = W2[i];

    const int wr = wid & 3, wc = wid >> 2;
    const uint32_t aA = smb + AH_OFF + (uint32_t)(wr * 16 + (lane & 15)) * LDSR
                      + ((lane >> 4) << 4);
    const uint32_t bBbase = smb + RING_OFF + (uint32_t)(lane & 15) * LDSR + wc * 128;

    float d[8][4];
#pragma unroll
    for (int nt = 0; nt < 8; ++nt)
#pragma unroll
        for (int q = 0; q < 4; ++q) d[nt][q] = 0.f;

    int slot_w = 3, slot_r = 0;
#pragma unroll 1
    for (int s = 0; s < 8; ++s) {
        if (s + 3 < 8) {
            int sp = s + 3;
            int r = tid >> 4, c = tid & 15;
            size_t goff = ((size_t)sp * 16 + r) * 128 + c * 8;
            uint32_t dst = smb + RING_OFF + slot_w * SLOT_SZ + r * LDSR + c * 16;
            cpa16(dst, Bhi + goff);
            cpa16(dst + 4352, Blo + goff);
        }
        CP_COMMIT();
        CP_WAIT3();
        __syncthreads();

        uint32_t ah[4], al[4];
        uint32_t ak = aA + s * 32;
        ldsm_x4(ah, ak);
        ldsm_x4(al, ak + (AL_OFF - AH_OFF));
        uint32_t bk = bBbase + (uint32_t)slot_r * SLOT_SZ;
#pragma unroll
        for (int nt = 0; nt < 8; ++nt) {
            uint32_t bh[2], bl[2];
            ldsm_x2t(bh, bk + nt * 16);
            ldsm_x2t(bl, bk + nt * 16 + 4352);
            mma_bf(d[nt], ah, bh);
            mma_bf(d[nt], ah, bl);
            mma_bf(d[nt], al, bh);
        }
        slot_w = (slot_w == 4) ? 0 : slot_w + 1;
        slot_r = (slot_r == 4) ? 0 : slot_r + 1;
    }

    // epilogue: T1 = leaky(D + b1) stays in registers; reduce T1 @ W2 per row
    float s0[3] = {0.f, 0.f, 0.f}, s1[3] = {0.f, 0.f, 0.f};
#pragma unroll
    for (int nt = 0; nt < 8; ++nt) {
        int c = wc * 64 + nt * 8 + (lane & 3) * 2;
        float u0 = d[nt][0] + sbias[c];     u0 = u0 > 0.f ? u0 : 0.2f * u0;
        float u1 = d[nt][1] + sbias[c + 1]; u1 = u1 > 0.f ? u1 : 0.2f * u1;
        float u2 = d[nt][2] + sbias[c];     u2 = u2 > 0.f ? u2 : 0.2f * u2;
        float u3 = d[nt][3] + sbias[c + 1]; u3 = u3 > 0.f ? u3 : 0.2f * u3;
#pragma unroll
        for (int k = 0; k < 3; ++k) {
            s0[k] += u0 * sW2[c * 3 + k] + u1 * sW2[(c + 1) * 3 + k];
            s1[k] += u2 * sW2[c * 3 + k] + u3 * sW2[(c + 1) * 3 + k];
        }
    }
    // reduce across the 4 lanes of each quad (lane&3)
#pragma unroll
    for (int k = 0; k < 3; ++k) {
        s0[k] += __shfl_xor_sync(0xffffffffu, s0[k], 1);
        s0[k] += __shfl_xor_sync(0xffffffffu, s0[k], 2);
        s1[k] += __shfl_xor_sync(0xffffffffu, s1[k], 1);
        s1[k] += __shfl_xor_sync(0xffffffffu, s1[k], 2);
    }
    if ((lane & 3) == 0) {
        int rl0 = wr * 16 + (lane >> 2);
#pragma unroll
        for (int k = 0; k < 3; ++k) {
            sred[rl0][wc][k]     = s0[k];
            sred[rl0 + 8][wc][k] = s1[k];
        }
    }
    __syncthreads();
    if (tid < 192) {
        int r = tid / 3, k = tid - r * 3;
        int gr = row0 + r;
        out[gr * 3 + k] = sred[r][0][k] + sred[r][1][k] + b2[k] + pos[gr * 3 + k];
    }
}

// ---------------- KNN (R8-proven, verbatim): 4 queries / 128-thread block --------------
__global__ __launch_bounds__(128) void knn_kernel(const float* __restrict__ pos) {
    __shared__ float4 p4[NN];
    __shared__ float qd[4][KQ][32];
    __shared__ int   qi[4][KQ][32];
    int tid = threadIdx.x;
    int b = blockIdx.x >> 9;
    int grp = blockIdx.x & 511;
    const float* pb = pos + (size_t)b * NN * 3;
    for (int j = tid; j < NN; j += 128) {
        float X = pb[j * 3], Y = pb[j * 3 + 1], Z = pb[j * 3 + 2];
        p4[j] = make_float4(X, Y, Z, X * X + Y * Y + Z * Z);
    }
    __syncthreads();
    int w = tid >> 5, lane = tid & 31;
    int il = grp * 4 + w;
    float4 q = p4[il];

    float qdr[KQ]; int qir[KQ];
#pragma unroll
    for (int p = 0; p < KQ; ++p) { qdr[p] = BIGF; qir[p] = 0x7fffffff; }

#pragma unroll 2
    for (int t = 0; t < NN / 32; ++t) {
        int j = lane + (t << 5);
        float4 pj = p4[j];
        float d2 = q.w + pj.w - 2.f * (q.x * pj.x + q.y * pj.y + q.z * pj.z);
        if (j != il && d2 < qdr[KQ - 1]) {
            float cd = d2; int ci = j;
#pragma unroll
            for (int p = 0; p < KQ; ++p) {
                bool lt = cd < qdr[p];
                float td = qdr[p]; int ti = qir[p];
                qdr[p] = lt ? cd : td; qir[p] = lt ? ci : ti;
                cd = lt ? td : cd;     ci = lt ? ti : ci;
            }
        }
    }
#pragma unroll
    for (int p = 0; p < KQ; ++p) { qd[w][p][lane] = qdr[p]; qi[w][p][lane] = qir[p]; }
    __syncwarp();

    int ptr = 0;
    float head = qdr[0]; int hidx = qir[0];
    int outj = 0;
    float lastd = 0.f; int lasti = 0;
    for (int r = 0; r < 32; ++r) {
        float bd = head; int bi = hidx; int bl = lane;
#pragma unroll
        for (int o = 16; o; o >>= 1) {
            float od = __shfl_xor_sync(0xffffffffu, bd, o);
            int oi = __shfl_xor_sync(0xffffffffu, bi, o);
            int ol = __shfl_xor_sync(0xffffffffu, bl, o);
            if (od < bd || (od == bd && oi < bi)) { bd = od; bi = oi; bl = ol; }
        }
        if (lane == r) outj = bi;
        if (lane == bl) {
            ++ptr;
            if (ptr < KQ) { head = qd[w][ptr][lane]; hidx = qi[w][ptr][lane]; }
            else          { head = BIGF; hidx = 0x7fffffff; }
        }
        lastd = bd; lasti = bi;
    }
    float lmd = qdr[KQ - 1]; int lmi = qir[KQ - 1];
    bool unsafe = (lmd < lastd) || (lmd == lastd && lmi < lasti);
    if (__ballot_sync(0xffffffffu, unsafe)) {
        float pd = -BIGF; int pi = -1;
        for (int r = 0; r < 32; ++r) {
            float bd = BIGF; int bi = 0x7fffffff;
            for (int t = 0; t < NN / 32; ++t) {
                int j = lane + (t << 5);
                float4 pj = p4[j];
                float d2 = q.w + pj.w - 2.f * (q.x * pj.x + q.y * pj.y + q.z * pj.z);
                if (j == il) d2 += 1e10f;
                bool gt = (d2 > pd) || (d2 == pd && j > pi);
                if (gt && (d2 < bd || (d2 == bd && j < bi))) { bd = d2; bi = j; }
            }
#pragma unroll
            for (int o = 16; o; o >>= 1) {
                float od = __shfl_xor_sync(0xffffffffu, bd, o);
                int oi = __shfl_xor_sync(0xffffffffu, bi, o);
                if (od < bd || (od == bd && oi < bi)) { bd = od; bi = oi; }
            }
            if (lane == r) outj = bi;
            pd = bd; pi = bi;
        }
    }
    g_nbr[((size_t)b * NN + il) * 32 + lane] = b * NN + outj;
}

// ---------------- neighborhood aggregation (both dilations fused, R8 verbatim) ---------
__global__ __launch_bounds__(128) void aggregate_kernel(
    const float* __restrict__ pos, const float* __restrict__ W_pos,
    const float* __restrict__ b_pos)
{
    __shared__ float sWp[3][128];
    __shared__ float sbp[128];
    int tid = threadIdx.x;
    sbp[tid] = b_pos[tid] + b_pos[128 + tid];
#pragma unroll
    for (int r = 0; r < 3; ++r)
        sWp[r][tid] = W_pos[r * 128 + tid] + W_pos[384 + r * 128 + tid];
    __syncthreads();

    int w = tid >> 5, lane = tid & 31;
    int i = blockIdx.x * 4 + w;
    int myn = g_nbr[(size_t)i * 32 + lane];
    int c = lane << 2;

    float4 a0 = {0,0,0,0}, s0 = {0,0,0,0};
#pragma unroll
    for (int k = 0; k <= 16; ++k) {
        int j = (k < 16) ? __shfl_sync(0xffffffffu, myn, k) : i;
        const float* pr = g_P + (size_t)j * NCOLS + c;
        float4 e = *(const float4*)pr;
        float4 m = *(const float4*)(pr + 128);
        s0.x += e.x; s0.y += e.y; s0.z += e.z; s0.w += e.w;
        a0.x += e.x * m.x; a0.y += e.y * m.y; a0.z += e.z * m.z; a0.w += e.w * m.w;
    }
    float4 a1 = {0,0,0,0}, s1 = {0,0,0,0};
#pragma unroll
    for (int k = 0; k <= 16; ++k) {
        int j = (k < 16) ? __shfl_sync(0xffffffffu, myn, 2 * k) : i;
        const float* pr = g_P + (size_t)j * NCOLS + 256 + c;
        float4 e = *(const float4*)pr;
        float4 m = *(const float4*)(pr + 128);
        s1.x += e.x; s1.y += e.y; s1.z += e.z; s1.w += e.w;
        a1.x += e.x * m.x; a1.y += e.y * m.y; a1.z += e.z * m.z; a1.w += e.w * m.w;
    }

    const float* pri = g_P + (size_t)i * NCOLS;
    float4 h2 = *(const float4*)(pri + 512 + c);
    float pix = pos[i * 3], piy = pos[i * 3 + 1], piz = pos[i * 3 + 2];
    float4 outv;
    outv.x = h2.x + a0.x / s0.x + a1.x / s1.x + sbp[c + 0]
           + pix * sWp[0][c + 0] + piy * sWp[1][c + 0] + piz * sWp[2][c + 0];
    outv.y = h2.y + a0.y / s0.y + a1.y / s1.y + sbp[c + 1]
           + pix * sWp[0][c + 1] + piy * sWp[1][c + 1] + piz * sWp[2][c + 1];
    outv.z = h2.z + a0.z / s0.z + a1.z / s1.z + sbp[c + 2]
           + pix * sWp[0][c + 2] + piy * sWp[1][c + 2] + piz * sWp[2][c + 2];
    outv.w = h2.w + a0.w / s0.w + a1.w / s1.w + sbp[c + 3]
           + pix * sWp[0][c + 3] + piy * sWp[1][c + 3] + piz * sWp[2][c + 3];
    *(float4*)(g_H + (size_t)i * CC + c) = outv;
}

// ---------------- launcher ----------------
extern "C" void kernel_launch(void* const* d_in, const int* in_sizes, int n_in,
                              void* d_out, int out_size) {
    const float* x     = (const float*)d_in[0];
    const float* pos   = (const float*)d_in[1];
    const float* W_lin = (const float*)d_in[2];
    const float* W_src = (const float*)d_in[3];
    // d_in[4] = W_dst: cancels in the per-channel softmax, unused
    const float* W_pos = (const float*)d_in[5];
    const float* b_pos = (const float*)d_in[6];
    const float* Wg    = (const float*)d_in[7];
    const float* bg    = (const float*)d_in[8];
    const float* W1    = (const float*)d_in[9];
    const float* b1    = (const float*)d_in[10];
    const float* W2    = (const float*)d_in[11];
    const float* b2    = (const float*)d_in[12];
    float* out = (float*)d_out;

    cudaFuncSetAttribute(gemm_p0,    cudaFuncAttributeMaxDynamicSharedMemorySize, SMEM_DYN);
    cudaFuncSetAttribute(gemm1_final, cudaFuncAttributeMaxDynamicSharedMemorySize, SMEM_DYN);

    pack_all<<<(6 * 16384 + 5 * 384 + 255) / 256, 256>>>(W_lin, W_src, Wg, W1, W_pos);
    knn_kernel<<<NPTS / 4, 128>>>(pos);

    __nv_bfloat16 *B0h, *B0l, *B1h, *B1l;
    float *Wp3, *P, *H;
    cudaGetSymbolAddress((void**)&B0h, g_B0hi);
    cudaGetSymbolAddress((void**)&B0l, g_B0lo);
    cudaGetSymbolAddress((void**)&B1h, g_B1hi);
    cudaGetSymbolAddress((void**)&B1l, g_B1lo);
    cudaGetSymbolAddress((void**)&Wp3, g_Wp3);
    cudaGetSymbolAddress((void**)&P,   g_P);
    cudaGetSymbolAddress((void**)&H,   g_H);

    gemm_p0<<<NPTS / 64, 256, SMEM_DYN>>>(x, B0h, B0l, bg, Wp3, pos, P);
    aggregate_kernel<<<NPTS / 4, 128>>>(pos, W_pos, b_pos);
    gemm1_final<<<NPTS / 64, 256, SMEM_DYN>>>(H, B1h, B1l, b1, W2, b2, pos, out);
}

// round 13
// speedup vs baseline: 1.3364x; 1.1619x over previous
#include <cuda_runtime.h>
#include <cuda_bf16.h>
#include <cstdint>

// Problem constants
#define BB 8
#define NN 2048
#define CC 128
#define NPTS (BB*NN)        // 16384
#define NCOLS 640           // e0|m0|e1|m1|h2pre
#define BIGF 3.402823466e38f

// gemm smem (R8-proven M64 layout): A tile 64x128 bf16 hi/lo, B ring of 5 chunks
#define LDSR 272
#define AH_OFF 0
#define AL_OFF 17408
#define RING_OFF 34816
#define SLOT_SZ 8704
#define SMEM_DYN (RING_OFF + 5 * SLOT_SZ)   // 78336

// ---------------- scratch (no allocations allowed) ----------------
__device__ __nv_bfloat16 g_B0hi[5 * 16384];
__device__ __nv_bfloat16 g_B0lo[5 * 16384];
__device__ __nv_bfloat16 g_B1hi[16384];
__device__ __nv_bfloat16 g_B1lo[16384];
__device__ float g_Wp3[5 * 3 * 128];
__device__ float g_P  [(size_t)NPTS * NCOLS];
__device__ int   g_nbr[NPTS * 32];
__device__ float g_H  [NPTS * CC];

// ---------------- combined weight packing (split-bf16 tiles + Wp3) ----------------
__global__ void pack_all(const float* __restrict__ W_lin, const float* __restrict__ W_src,
                         const float* __restrict__ Wg, const float* __restrict__ W1,
                         const float* __restrict__ W_pos) {
    int t = blockIdx.x * blockDim.x + threadIdx.x;
    if (t < 6 * 16384) {
        int tile = t >> 14, idx = t & 16383;
        float w;
        if (tile < 4) {
            int li = tile >> 1;
            w = (tile & 1) ? W_lin[li * 16384 + idx] : W_src[li * 16384 + idx];
        } else if (tile == 4) {
            w = Wg[idx];
        } else {
            w = W1[idx];
        }
        __nv_bfloat16 hi = __float2bfloat16(w);
        __nv_bfloat16 lo = __float2bfloat16(w - __bfloat162float(hi));
        if (tile < 5) { g_B0hi[tile * 16384 + idx] = hi; g_B0lo[tile * 16384 + idx] = lo; }
        else          { g_B1hi[idx] = hi; g_B1lo[idx] = lo; }
    } else if (t < 6 * 16384 + 5 * 384) {
        int u = t - 6 * 16384;
        int cg = u / 384, i = u - cg * 384;
        int td = i >> 7, c = i & 127;
        float v;
        if (cg < 4) {
            int li = cg >> 1;
            float wp = W_pos[li * 384 + td * 128 + c];
            v = (cg & 1) ? -wp : wp;
        } else {
            v = Wg[(128 + td) * 128 + c];
        }
        g_Wp3[u] = v;
    }
}

// ---------------- mma / async helpers ----------------
__device__ __forceinline__ uint32_t smem_u32(const void* p) {
    uint32_t a;
    asm("{ .reg .u64 t; cvta.to.shared.u64 t, %1; cvt.u32.u64 %0, t; }" : "=r"(a) : "l"(p));
    return a;
}
__device__ __forceinline__ void cpa16(uint32_t d, const void* s) {
    uint64_t g;
    asm("cvta.to.global.u64 %0, %1;" : "=l"(g) : "l"(s));
    asm volatile("cp.async.cg.shared.global [%0], [%1], 16;" :: "r"(d), "l"(g));
}
#define CP_COMMIT() asm volatile("cp.async.commit_group;" ::: "memory")
#define CP_WAIT3()  asm volatile("cp.async.wait_group 3;" ::: "memory")
__device__ __forceinline__ void ldsm_x4(uint32_t r[4], uint32_t a) {
    asm volatile("ldmatrix.sync.aligned.m8n8.x4.shared.b16 {%0,%1,%2,%3}, [%4];"
        : "=r"(r[0]), "=r"(r[1]), "=r"(r[2]), "=r"(r[3]) : "r"(a));
}
__device__ __forceinline__ void ldsm_x2t(uint32_t r[2], uint32_t a) {
    asm volatile("ldmatrix.sync.aligned.m8n8.x2.trans.shared.b16 {%0,%1}, [%2];"
        : "=r"(r[0]), "=r"(r[1]) : "r"(a));
}
__device__ __forceinline__ void mma_bf(float d[4], const uint32_t a[4], const uint32_t b[2]) {
    asm volatile("mma.sync.aligned.m16n8k16.row.col.f32.bf16.bf16.f32 "
        "{%0,%1,%2,%3}, {%4,%5,%6,%7}, {%8,%9}, {%0,%1,%2,%3};"
        : "+f"(d[0]), "+f"(d[1]), "+f"(d[2]), "+f"(d[3])
        : "r"(a[0]), "r"(a[1]), "r"(a[2]), "r"(a[3]), "r"(b[0]), "r"(b[1]));
}
__device__ __forceinline__ uint32_t bfpack(float x, float y) {
    __nv_bfloat16 hx = __float2bfloat16(x), hy = __float2bfloat16(y);
    return ((uint32_t)__bfloat16_as_ushort(hy) << 16) | __bfloat16_as_ushort(hx);
}

// ---------------- gemm0: persistent-row split-bf16, M-tile 64, 5 col groups (R8) --------
__global__ __launch_bounds__(256) void gemm_p0(
    const float* __restrict__ A,
    const __nv_bfloat16* __restrict__ Bhi, const __nv_bfloat16* __restrict__ Blo,
    const float* __restrict__ bias, const float* __restrict__ Wp3,
    const float* __restrict__ pos, float* __restrict__ C)
{
    extern __shared__ char sm[];
    __shared__ float sWb[5 * 384 + 128];
    const int tid = threadIdx.x;
    const int lane = tid & 31, wid = tid >> 5;
    const int row0 = blockIdx.x * 64;
    const int NSTEP = 5 * 8;
    const int ldc = NCOLS;
    const uint32_t smb = smem_u32(sm);

    {
        int r = tid >> 4, c = tid & 15;
#pragma unroll
        for (int s = 0; s < 3; ++s) {
            int cg = s >> 3, ks = s & 7;
            size_t goff = ((size_t)cg * 128 + ks * 16 + r) * 128 + c * 8;
            uint32_t dst = smb + RING_OFF + s * SLOT_SZ + r * LDSR + c * 16;
            cpa16(dst, Bhi + goff);
            cpa16(dst + 4352, Blo + goff);
            CP_COMMIT();
        }
    }
    {
        int r = tid >> 2, qch = tid & 3;
        const float* Ar = A + (size_t)(row0 + r) * 128 + qch * 32;
        uint32_t* Ah = (uint32_t*)(sm + AH_OFF + r * LDSR + qch * 64);
        uint32_t* Al = (uint32_t*)(sm + AL_OFF + r * LDSR + qch * 64);
#pragma unroll
        for (int f = 0; f < 8; ++f) {
            float4 v = *(const float4*)(Ar + f * 4);
            float hx = __bfloat162float(__float2bfloat16(v.x));
            float hy = __bfloat162float(__float2bfloat16(v.y));
            float hz = __bfloat162float(__float2bfloat16(v.z));
            float hw = __bfloat162float(__float2bfloat16(v.w));
            Ah[f * 2]     = bfpack(hx, hy);
            Ah[f * 2 + 1] = bfpack(hz, hw);
            Al[f * 2]     = bfpack(v.x - hx, v.y - hy);
            Al[f * 2 + 1] = bfpack(v.z - hz, v.w - hw);
        }
    }
    for (int i = tid; i < 1920; i += 256) sWb[i] = Wp3[i];
    if (tid < 128) sWb[1920 + tid] = bias[tid];

    const int wr = wid & 3, wc = wid >> 2;
    const uint32_t aA = smb + AH_OFF + (uint32_t)(wr * 16 + (lane & 15)) * LDSR
                      + ((lane >> 4) << 4);
    const uint32_t bBbase = smb + RING_OFF + (uint32_t)(lane & 15) * LDSR + wc * 128;

    float prx[2][3];
    {
        int r0 = row0 + wr * 16 + (lane >> 2);
        prx[0][0] = pos[r0 * 3];       prx[0][1] = pos[r0 * 3 + 1];
        prx[0][2] = pos[r0 * 3 + 2];
        prx[1][0] = pos[(r0 + 8) * 3]; prx[1][1] = pos[(r0 + 8) * 3 + 1];
        prx[1][2] = pos[(r0 + 8) * 3 + 2];
    }

    float d[8][4];
#pragma unroll
    for (int nt = 0; nt < 8; ++nt)
#pragma unroll
        for (int q = 0; q < 4; ++q) d[nt][q] = 0.f;

    int slot_w = 3, slot_r = 0;
#pragma unroll 1
    for (int s = 0; s < NSTEP; ++s) {
        if (s + 3 < NSTEP) {
            int sp = s + 3;
            int cg = sp >> 3, ks = sp & 7;
            int r = tid >> 4, c = tid & 15;
            size_t goff = ((size_t)cg * 128 + ks * 16 + r) * 128 + c * 8;
            uint32_t dst = smb + RING_OFF + slot_w * SLOT_SZ + r * LDSR + c * 16;
            cpa16(dst, Bhi + goff);
            cpa16(dst + 4352, Blo + goff);
        }
        CP_COMMIT();
        CP_WAIT3();
        __syncthreads();

        const int ks = s & 7;
        uint32_t ah[4], al[4];
        uint32_t ak = aA + ks * 32;
        ldsm_x4(ah, ak);
        ldsm_x4(al, ak + (AL_OFF - AH_OFF));
        uint32_t bk = bBbase + (uint32_t)slot_r * SLOT_SZ;
#pragma unroll
        for (int nt = 0; nt < 8; ++nt) {
            uint32_t bh[2], bl[2];
            ldsm_x2t(bh, bk + nt * 16);
            ldsm_x2t(bl, bk + nt * 16 + 4352);
            mma_bf(d[nt], ah, bh);
            mma_bf(d[nt], ah, bl);
            mma_bf(d[nt], al, bh);
        }
        slot_w = (slot_w == 4) ? 0 : slot_w + 1;
        slot_r = (slot_r == 4) ? 0 : slot_r + 1;

        if (ks == 7) {
            const int cg = s >> 3;
            const float* sW0 = sWb + cg * 384;
            int r0 = row0 + wr * 16 + (lane >> 2);
            int r1 = r0 + 8;
#pragma unroll
            for (int nt = 0; nt < 8; ++nt) {
                int c = wc * 64 + nt * 8 + (lane & 3) * 2;
                float u0 = d[nt][0], u1 = d[nt][1];
                float u2 = d[nt][2], u3 = d[nt][3];
                u0 += prx[0][0] * sW0[c]     + prx[0][1] * sW0[128 + c]     + prx[0][2] * sW0[256 + c];
                u1 += prx[0][0] * sW0[c + 1] + prx[0][1] * sW0[128 + c + 1] + prx[0][2] * sW0[256 + c + 1];
                u2 += prx[1][0] * sW0[c]     + prx[1][1] * sW0[128 + c]     + prx[1][2] * sW0[256 + c];
                u3 += prx[1][0] * sW0[c + 1] + prx[1][1] * sW0[128 + c + 1] + prx[1][2] * sW0[256 + c + 1];
                if (cg == 4) {
                    u0 += sWb[1920 + c];     u0 = u0 > 0.f ? u0 : 0.2f * u0;
                    u1 += sWb[1920 + c + 1]; u1 = u1 > 0.f ? u1 : 0.2f * u1;
                    u2 += sWb[1920 + c];     u2 = u2 > 0.f ? u2 : 0.2f * u2;
                    u3 += sWb[1920 + c + 1]; u3 = u3 > 0.f ? u3 : 0.2f * u3;
                } else if (!(cg & 1)) {
                    u0 = __expf(-u0); u1 = __expf(-u1);
                    u2 = __expf(-u2); u3 = __expf(-u3);
                }
                *(float2*)(C + (size_t)r0 * ldc + cg * 128 + c) = make_float2(u0, u1);
                *(float2*)(C + (size_t)r1 * ldc + cg * 128 + c) = make_float2(u2, u3);
                d[nt][0] = 0.f; d[nt][1] = 0.f; d[nt][2] = 0.f; d[nt][3] = 0.f;
            }
        }
    }
}

// ---------------- gemm1 fused with final projection: out = T1@W2 + b2 + pos ------------
__global__ __launch_bounds__(256) void gemm1_final(
    const float* __restrict__ A,
    const __nv_bfloat16* __restrict__ Bhi, const __nv_bfloat16* __restrict__ Blo,
    const float* __restrict__ bias, const float* __restrict__ W2,
    const float* __restrict__ b2, const float* __restrict__ pos,
    float* __restrict__ out)
{
    extern __shared__ char sm[];
    __shared__ float sbias[128];
    __shared__ float sW2[384];
    __shared__ float sred[64][2][3];
    const int tid = threadIdx.x;
    const int lane = tid & 31, wid = tid >> 5;
    const int row0 = blockIdx.x * 64;
    const uint32_t smb = smem_u32(sm);

    {
        int r = tid >> 4, c = tid & 15;
#pragma unroll
        for (int s = 0; s < 3; ++s) {
            size_t goff = ((size_t)s * 16 + r) * 128 + c * 8;
            uint32_t dst = smb + RING_OFF + s * SLOT_SZ + r * LDSR + c * 16;
            cpa16(dst, Bhi + goff);
            cpa16(dst + 4352, Blo + goff);
            CP_COMMIT();
        }
    }
    {
        int r = tid >> 2, qch = tid & 3;
        const float* Ar = A + (size_t)(row0 + r) * 128 + qch * 32;
        uint32_t* Ah = (uint32_t*)(sm + AH_OFF + r * LDSR + qch * 64);
        uint32_t* Al = (uint32_t*)(sm + AL_OFF + r * LDSR + qch * 64);
#pragma unroll
        for (int f = 0; f < 8; ++f) {
            float4 v = *(const float4*)(Ar + f * 4);
            float hx = __bfloat162float(__float2bfloat16(v.x));
            float hy = __bfloat162float(__float2bfloat16(v.y));
            float hz = __bfloat162float(__float2bfloat16(v.z));
            float hw = __bfloat162float(__float2bfloat16(v.w));
            Ah[f * 2]     = bfpack(hx, hy);
            Ah[f * 2 + 1] = bfpack(hz, hw);
            Al[f * 2]     = bfpack(v.x - hx, v.y - hy);
            Al[f * 2 + 1] = bfpack(v.z - hz, v.w - hw);
        }
    }
    if (tid < 128) sbias[tid] = bias[tid];
    for (int i = tid; i < 384; i += 256) sW2[i] = W2[i];

    const int wr = wid & 3, wc = wid >> 2;
    const uint32_t aA = smb + AH_OFF + (uint32_t)(wr * 16 + (lane & 15)) * LDSR
                      + ((lane >> 4) << 4);
    const uint32_t bBbase = smb + RING_OFF + (uint32_t)(lane & 15) * LDSR + wc * 128;

    float d[8][4];
#pragma unroll
    for (int nt = 0; nt < 8; ++nt)
#pragma unroll
        for (int q = 0; q < 4; ++q) d[nt][q] = 0.f;

    int slot_w = 3, slot_r = 0;
#pragma unroll 1
    for (int s = 0; s < 8; ++s) {
        if (s + 3 < 8) {
            int sp = s + 3;
            int r = tid >> 4, c = tid & 15;
            size_t goff = ((size_t)sp * 16 + r) * 128 + c * 8;
            uint32_t dst = smb + RING_OFF + slot_w * SLOT_SZ + r * LDSR + c * 16;
            cpa16(dst, Bhi + goff);
            cpa16(dst + 4352, Blo + goff);
        }
        CP_COMMIT();
        CP_WAIT3();
        __syncthreads();

        uint32_t ah[4], al[4];
        uint32_t ak = aA + s * 32;
        ldsm_x4(ah, ak);
        ldsm_x4(al, ak + (AL_OFF - AH_OFF));
        uint32_t bk = bBbase + (uint32_t)slot_r * SLOT_SZ;
#pragma unroll
        for (int nt = 0; nt < 8; ++nt) {
            uint32_t bh[2], bl[2];
            ldsm_x2t(bh, bk + nt * 16);
            ldsm_x2t(bl, bk + nt * 16 + 4352);
            mma_bf(d[nt], ah, bh);
            mma_bf(d[nt], ah, bl);
            mma_bf(d[nt], al, bh);
        }
        slot_w = (slot_w == 4) ? 0 : slot_w + 1;
        slot_r = (slot_r == 4) ? 0 : slot_r + 1;
    }

    float s0[3] = {0.f, 0.f, 0.f}, s1[3] = {0.f, 0.f, 0.f};
#pragma unroll
    for (int nt = 0; nt < 8; ++nt) {
        int c = wc * 64 + nt * 8 + (lane & 3) * 2;
        float u0 = d[nt][0] + sbias[c];     u0 = u0 > 0.f ? u0 : 0.2f * u0;
        float u1 = d[nt][1] + sbias[c + 1]; u1 = u1 > 0.f ? u1 : 0.2f * u1;
        float u2 = d[nt][2] + sbias[c];     u2 = u2 > 0.f ? u2 : 0.2f * u2;
        float u3 = d[nt][3] + sbias[c + 1]; u3 = u3 > 0.f ? u3 : 0.2f * u3;
#pragma unroll
        for (int k = 0; k < 3; ++k) {
            s0[k] += u0 * sW2[c * 3 + k] + u1 * sW2[(c + 1) * 3 + k];
            s1[k] += u2 * sW2[c * 3 + k] + u3 * sW2[(c + 1) * 3 + k];
        }
    }
#pragma unroll
    for (int k = 0; k < 3; ++k) {
        s0[k] += __shfl_xor_sync(0xffffffffu, s0[k], 1);
        s0[k] += __shfl_xor_sync(0xffffffffu, s0[k], 2);
        s1[k] += __shfl_xor_sync(0xffffffffu, s1[k], 1);
        s1[k] += __shfl_xor_sync(0xffffffffu, s1[k], 2);
    }
    if ((lane & 3) == 0) {
        int rl0 = wr * 16 + (lane >> 2);
#pragma unroll
        for (int k = 0; k < 3; ++k) {
            sred[rl0][wc][k]     = s0[k];
            sred[rl0 + 8][wc][k] = s1[k];
        }
    }
    __syncthreads();
    if (tid < 192) {
        int r = tid / 3, k = tid - r * 3;
        int gr = row0 + r;
        out[gr * 3 + k] = sred[r][0][k] + sred[r][1][k] + b2[k] + pos[gr * 3 + k];
    }
}

// ---------------- KNN: warp-distributed sorted top-32 (exact, no merge) ----------------
// The warp's top-32 is kept SORTED across lanes as 64-bit keys (d2_ordered<<32|idx),
// lane 0 = smallest. Per 32-candidate batch: ballot survivors vs current max
// (lane 31); each survivor is broadcast and inserted via ballot-rank + shfl.up shift.
// ~165 expected inserts per query total. Exact top-32 under our d2 -> no fallback.
__global__ __launch_bounds__(128) void knn_kernel(const float* __restrict__ pos) {
    __shared__ float4 p4[NN];            // 32 KB only -> high occupancy
    int tid = threadIdx.x;
    int b = blockIdx.x >> 9;             // 512 blocks per batch, 4 queries each
    int grp = blockIdx.x & 511;
    const float* pb = pos + (size_t)b * NN * 3;
    for (int j = tid; j < NN; j += 128) {
        float X = pb[j * 3], Y = pb[j * 3 + 1], Z = pb[j * 3 + 2];
        p4[j] = make_float4(X, Y, Z, X * X + Y * Y + Z * Z);
    }
    __syncthreads();
    int w = tid >> 5, lane = tid & 31;
    int il = grp * 4 + w;
    float4 q = p4[il];

    unsigned long long qk = 0xFFFFFFFFFFFFFFFFull;   // sorted asc across lanes

#pragma unroll 2
    for (int t = 0; t < NN / 32; ++t) {
        int j = lane + (t << 5);
        float4 pj = p4[j];
        float d2 = q.w + pj.w - 2.f * (q.x * pj.x + q.y * pj.y + q.z * pj.z);
        unsigned ub = __float_as_uint(d2);
        ub ^= ((unsigned)((int)ub >> 31)) | 0x80000000u;   // order-preserving transform
        unsigned long long key = ((unsigned long long)ub << 32) | (unsigned)j;
        if (j == il) key = 0xFFFFFFFFFFFFFFFFull;          // exclude self
        unsigned long long kmax = __shfl_sync(0xffffffffu, qk, 31);
        unsigned surv = __ballot_sync(0xffffffffu, key < kmax);
        while (surv) {
            int src = __ffs(surv) - 1;
            surv &= surv - 1;
            unsigned long long ck = __shfl_sync(0xffffffffu, key, src);
            kmax = __shfl_sync(0xffffffffu, qk, 31);
            unsigned long long up = __shfl_up_sync(0xffffffffu, qk, 1);
            if (ck < kmax) {               // warp-uniform condition
                unsigned lm = __ballot_sync(0xffffffffu, qk < ck);
                int posn = __popc(lm);     // insertion position
                if (lane > posn)       qk = up;
                else if (lane == posn) qk = ck;
            }
        }
    }
    g_nbr[((size_t)b * NN + il) * 32 + lane] = b * NN + (int)(qk & 0xffffffffu);
}

// ---------------- neighborhood aggregation (both dilations fused, R8 verbatim) ---------
__global__ __launch_bounds__(128) void aggregate_kernel(
    const float* __restrict__ pos, const float* __restrict__ W_pos,
    const float* __restrict__ b_pos)
{
    __shared__ float sWp[3][128];
    __shared__ float sbp[128];
    int tid = threadIdx.x;
    sbp[tid] = b_pos[tid] + b_pos[128 + tid];
#pragma unroll
    for (int r = 0; r < 3; ++r)
        sWp[r][tid] = W_pos[r * 128 + tid] + W_pos[384 + r * 128 + tid];
    __syncthreads();

    int w = tid >> 5, lane = tid & 31;
    int i = blockIdx.x * 4 + w;
    int myn = g_nbr[(size_t)i * 32 + lane];
    int c = lane << 2;

    float4 a0 = {0,0,0,0}, s0 = {0,0,0,0};
#pragma unroll
    for (int k = 0; k <= 16; ++k) {
        int j = (k < 16) ? __shfl_sync(0xffffffffu, myn, k) : i;
        const float* pr = g_P + (size_t)j * NCOLS + c;
        float4 e = *(const float4*)pr;
        float4 m = *(const float4*)(pr + 128);
        s0.x += e.x; s0.y += e.y; s0.z += e.z; s0.w += e.w;
        a0.x += e.x * m.x; a0.y += e.y * m.y; a0.z += e.z * m.z; a0.w += e.w * m.w;
    }
    float4 a1 = {0,0,0,0}, s1 = {0,0,0,0};
#pragma unroll
    for (int k = 0; k <= 16; ++k) {
        int j = (k < 16) ? __shfl_sync(0xffffffffu, myn, 2 * k) : i;
        const float* pr = g_P + (size_t)j * NCOLS + 256 + c;
        float4 e = *(const float4*)pr;
        float4 m = *(const float4*)(pr + 128);
        s1.x += e.x; s1.y += e.y; s1.z += e.z; s1.w += e.w;
        a1.x += e.x * m.x; a1.y += e.y * m.y; a1.z += e.z * m.z; a1.w += e.w * m.w;
    }

    const float* pri = g_P + (size_t)i * NCOLS;
    float4 h2 = *(const float4*)(pri + 512 + c);
    float pix = pos[i * 3], piy = pos[i * 3 + 1], piz = pos[i * 3 + 2];
    float4 outv;
    outv.x = h2.x + a0.x / s0.x + a1.x / s1.x + sbp[c + 0]
           + pix * sWp[0][c + 0] + piy * sWp[1][c + 0] + piz * sWp[2][c + 0];
    outv.y = h2.y + a0.y / s0.y + a1.y / s1.y + sbp[c + 1]
           + pix * sWp[0][c + 1] + piy * sWp[1][c + 1] + piz * sWp[2][c + 1];
    outv.z = h2.z + a0.z / s0.z + a1.z / s1.z + sbp[c + 2]
           + pix * sWp[0][c + 2] + piy * sWp[1][c + 2] + piz * sWp[2][c + 2];
    outv.w = h2.w + a0.w / s0.w + a1.w / s1.w + sbp[c + 3]
           + pix * sWp[0][c + 3] + piy * sWp[1][c + 3] + piz * sWp[2][c + 3];
    *(float4*)(g_H + (size_t)i * CC + c) = outv;
}

// ---------------- launcher ----------------
extern "C" void kernel_launch(void* const* d_in, const int* in_sizes, int n_in,
                              void* d_out, int out_size) {
    const float* x     = (const float*)d_in[0];
    const float* pos   = (const float*)d_in[1];
    const float* W_lin = (const float*)d_in[2];
    const float* W_src = (const float*)d_in[3];
    // d_in[4] = W_dst: cancels in the per-channel softmax, unused
    const float* W_pos = (const float*)d_in[5];
    const float* b_pos = (const float*)d_in[6];
    const float* Wg    = (const float*)d_in[7];
    const float* bg    = (const float*)d_in[8];
    const float* W1    = (const float*)d_in[9];
    const float* b1    = (const float*)d_in[10];
    const float* W2    = (const float*)d_in[11];
    const float* b2    = (const float*)d_in[12];
    float* out = (float*)d_out;

    cudaFuncSetAttribute(gemm_p0,     cudaFuncAttributeMaxDynamicSharedMemorySize, SMEM_DYN);
    cudaFuncSetAttribute(gemm1_final, cudaFuncAttributeMaxDynamicSharedMemorySize, SMEM_DYN);

    pack_all<<<(6 * 16384 + 5 * 384 + 255) / 256, 256>>>(W_lin, W_src, Wg, W1, W_pos);
    knn_kernel<<<NPTS / 4, 128>>>(pos);

    __nv_bfloat16 *B0h, *B0l, *B1h, *B1l;
    float *Wp3, *P, *H;
    cudaGetSymbolAddress((void**)&B0h, g_B0hi);
    cudaGetSymbolAddress((void**)&B0l, g_B0lo);
    cudaGetSymbolAddress((void**)&B1h, g_B1hi);
    cudaGetSymbolAddress((void**)&B1l, g_B1lo);
    cudaGetSymbolAddress((void**)&Wp3, g_Wp3);
    cudaGetSymbolAddress((void**)&P,   g_P);
    cudaGetSymbolAddress((void**)&H,   g_H);

    gemm_p0<<<NPTS / 64, 256, SMEM_DYN>>>(x, B0h, B0l, bg, Wp3, pos, P);
    aggregate_kernel<<<NPTS / 4, 128>>>(pos, W_pos, b_pos);
    gemm1_final<<<NPTS / 64, 256, SMEM_DYN>>>(H, B1h, B1l, b1, W2, b2, pos, out);
}

// round 14
// speedup vs baseline: 1.5052x; 1.1263x over previous
#include <cuda_runtime.h>
#include <cuda_bf16.h>
#include <cstdint>

// Problem constants
#define BB 8
#define NN 2048
#define CC 128
#define NPTS (BB*NN)        // 16384
#define NCOLS 640           // e0|m0|e1|m1|h2pre
#define BIGF 3.402823466e38f

// gemm smem: A tile 64x128 bf16 hi/lo; B ring of 4 slots, 32 k-rows per slot
#define LDSR 272
#define AH_OFF 0
#define AL_OFF 17408
#define RING_OFF 34816
#define SLOT_SZ 17408       // hi (32*272=8704) + lo (8704)
#define SMEM_DYN (RING_OFF + 4 * SLOT_SZ)   // 104448 -> 2 CTAs/SM

// ---------------- scratch (no allocations allowed) ----------------
__device__ __nv_bfloat16 g_B0hi[5 * 16384];
__device__ __nv_bfloat16 g_B0lo[5 * 16384];
__device__ __nv_bfloat16 g_B1hi[16384];
__device__ __nv_bfloat16 g_B1lo[16384];
__device__ float g_Wp3[5 * 3 * 128];
__device__ float g_P  [(size_t)NPTS * NCOLS];
__device__ int   g_nbr[NPTS * 32];
__device__ float g_H  [NPTS * CC];

// ---------------- combined weight packing (split-bf16 tiles + Wp3) ----------------
__global__ void pack_all(const float* __restrict__ W_lin, const float* __restrict__ W_src,
                         const float* __restrict__ Wg, const float* __restrict__ W1,
                         const float* __restrict__ W_pos) {
    int t = blockIdx.x * blockDim.x + threadIdx.x;
    if (t < 6 * 16384) {
        int tile = t >> 14, idx = t & 16383;
        float w;
        if (tile < 4) {
            int li = tile >> 1;
            w = (tile & 1) ? W_lin[li * 16384 + idx] : W_src[li * 16384 + idx];
        } else if (tile == 4) {
            w = Wg[idx];
        } else {
            w = W1[idx];
        }
        __nv_bfloat16 hi = __float2bfloat16(w);
        __nv_bfloat16 lo = __float2bfloat16(w - __bfloat162float(hi));
        if (tile < 5) { g_B0hi[tile * 16384 + idx] = hi; g_B0lo[tile * 16384 + idx] = lo; }
        else          { g_B1hi[idx] = hi; g_B1lo[idx] = lo; }
    } else if (t < 6 * 16384 + 5 * 384) {
        int u = t - 6 * 16384;
        int cg = u / 384, i = u - cg * 384;
        int td = i >> 7, c = i & 127;
        float v;
        if (cg < 4) {
            int li = cg >> 1;
            float wp = W_pos[li * 384 + td * 128 + c];
            v = (cg & 1) ? -wp : wp;
        } else {
            v = Wg[(128 + td) * 128 + c];
        }
        g_Wp3[u] = v;
    }
}

// ---------------- mma / async helpers ----------------
__device__ __forceinline__ uint32_t smem_u32(const void* p) {
    uint32_t a;
    asm("{ .reg .u64 t; cvta.to.shared.u64 t, %1; cvt.u32.u64 %0, t; }" : "=r"(a) : "l"(p));
    return a;
}
__device__ __forceinline__ void cpa16(uint32_t d, const void* s) {
    uint64_t g;
    asm("cvta.to.global.u64 %0, %1;" : "=l"(g) : "l"(s));
    asm volatile("cp.async.cg.shared.global [%0], [%1], 16;" :: "r"(d), "l"(g));
}
#define CP_COMMIT() asm volatile("cp.async.commit_group;" ::: "memory")
#define CP_WAIT2()  asm volatile("cp.async.wait_group 2;" ::: "memory")
__device__ __forceinline__ void ldsm_x4(uint32_t r[4], uint32_t a) {
    asm volatile("ldmatrix.sync.aligned.m8n8.x4.shared.b16 {%0,%1,%2,%3}, [%4];"
        : "=r"(r[0]), "=r"(r[1]), "=r"(r[2]), "=r"(r[3]) : "r"(a));
}
__device__ __forceinline__ void ldsm_x2t(uint32_t r[2], uint32_t a) {
    asm volatile("ldmatrix.sync.aligned.m8n8.x2.trans.shared.b16 {%0,%1}, [%2];"
        : "=r"(r[0]), "=r"(r[1]) : "r"(a));
}
__device__ __forceinline__ void mma_bf(float d[4], const uint32_t a[4], const uint32_t b[2]) {
    asm volatile("mma.sync.aligned.m16n8k16.row.col.f32.bf16.bf16.f32 "
        "{%0,%1,%2,%3}, {%4,%5,%6,%7}, {%8,%9}, {%0,%1,%2,%3};"
        : "+f"(d[0]), "+f"(d[1]), "+f"(d[2]), "+f"(d[3])
        : "r"(a[0]), "r"(a[1]), "r"(a[2]), "r"(a[3]), "r"(b[0]), "r"(b[1]));
}
__device__ __forceinline__ uint32_t bfpack(float x, float y) {
    __nv_bfloat16 hx = __float2bfloat16(x), hy = __float2bfloat16(y);
    return ((uint32_t)__bfloat16_as_ushort(hy) << 16) | __bfloat16_as_ushort(hx);
}

// issue one 32-k-row B slot (hi+lo) via cp.async; 4 cpa16 per thread
__device__ __forceinline__ void issue_slot(uint32_t slotbase,
                                           const __nv_bfloat16* __restrict__ Bhi,
                                           const __nv_bfloat16* __restrict__ Blo,
                                           size_t gbase, int tid) {
    int r = tid >> 4, c = tid & 15;
#pragma unroll
    for (int h = 0; h < 32; h += 16) {
        size_t goff = gbase + (size_t)(r + h) * 128 + c * 8;
        uint32_t dst = slotbase + (r + h) * LDSR + c * 16;
        cpa16(dst, Bhi + goff);
        cpa16(dst + 8704, Blo + goff);
    }
}

// ---------------- gemm0: persistent-row split-bf16, M-tile 64, KCH=32, ring 4 -----------
__global__ __launch_bounds__(256) void gemm_p0(
    const float* __restrict__ A,
    const __nv_bfloat16* __restrict__ Bhi, const __nv_bfloat16* __restrict__ Blo,
    const float* __restrict__ bias, const float* __restrict__ Wp3,
    const float* __restrict__ pos, float* __restrict__ C)
{
    extern __shared__ char sm[];
    __shared__ float sWb[5 * 384 + 128];
    const int tid = threadIdx.x;
    const int lane = tid & 31, wid = tid >> 5;
    const int row0 = blockIdx.x * 64;
    const int NSTEP = 5 * 4;            // 5 col groups x (128/32) k-chunks
    const int ldc = NCOLS;
    const uint32_t smb = smem_u32(sm);

    // prologue: slots for steps 0,1
    issue_slot(smb + RING_OFF + 0 * SLOT_SZ, Bhi, Blo, (size_t)0 * 16384 + 0 * 32 * 128, tid);
    CP_COMMIT();
    issue_slot(smb + RING_OFF + 1 * SLOT_SZ, Bhi, Blo, (size_t)0 * 16384 + 1 * 32 * 128, tid);
    CP_COMMIT();

    // stage + split A (64 rows), once per CTA
    {
        int r = tid >> 2, qch = tid & 3;
        const float* Ar = A + (size_t)(row0 + r) * 128 + qch * 32;
        uint32_t* Ah = (uint32_t*)(sm + AH_OFF + r * LDSR + qch * 64);
        uint32_t* Al = (uint32_t*)(sm + AL_OFF + r * LDSR + qch * 64);
#pragma unroll
        for (int f = 0; f < 8; ++f) {
            float4 v = *(const float4*)(Ar + f * 4);
            float hx = __bfloat162float(__float2bfloat16(v.x));
            float hy = __bfloat162float(__float2bfloat16(v.y));
            float hz = __bfloat162float(__float2bfloat16(v.z));
            float hw = __bfloat162float(__float2bfloat16(v.w));
            Ah[f * 2]     = bfpack(hx, hy);
            Ah[f * 2 + 1] = bfpack(hz, hw);
            Al[f * 2]     = bfpack(v.x - hx, v.y - hy);
            Al[f * 2 + 1] = bfpack(v.z - hz, v.w - hw);
        }
    }
    for (int i = tid; i < 1920; i += 256) sWb[i] = Wp3[i];
    if (tid < 128) sWb[1920 + tid] = bias[tid];

    const int wr = wid & 3, wc = wid >> 2;
    const uint32_t aA = smb + AH_OFF + (uint32_t)(wr * 16 + (lane & 15)) * LDSR
                      + ((lane >> 4) << 4);
    const uint32_t bBbase = smb + RING_OFF + (uint32_t)(lane & 15) * LDSR + wc * 128;

    float prx[2][3];
    {
        int r0 = row0 + wr * 16 + (lane >> 2);
        prx[0][0] = pos[r0 * 3];       prx[0][1] = pos[r0 * 3 + 1];
        prx[0][2] = pos[r0 * 3 + 2];
        prx[1][0] = pos[(r0 + 8) * 3]; prx[1][1] = pos[(r0 + 8) * 3 + 1];
        prx[1][2] = pos[(r0 + 8) * 3 + 2];
    }

    float d[8][4];
#pragma unroll
    for (int nt = 0; nt < 8; ++nt)
#pragma unroll
        for (int q = 0; q < 4; ++q) d[nt][q] = 0.f;

#pragma unroll 1
    for (int s = 0; s < NSTEP; ++s) {
        if (s + 2 < NSTEP) {
            int sp = s + 2;
            int cg = sp >> 2, ks = sp & 3;
            issue_slot(smb + RING_OFF + (sp & 3) * SLOT_SZ, Bhi, Blo,
                       (size_t)cg * 16384 + (size_t)ks * 32 * 128, tid);
        }
        CP_COMMIT();
        CP_WAIT2();
        __syncthreads();

        const int ks = s & 3;
        const uint32_t slotb = bBbase + (uint32_t)(s & 3) * SLOT_SZ;
#pragma unroll
        for (int ks2 = 0; ks2 < 2; ++ks2) {
            int k16 = ks * 2 + ks2;
            uint32_t ah[4], al[4];
            uint32_t ak = aA + k16 * 32;
            ldsm_x4(ah, ak);
            ldsm_x4(al, ak + (AL_OFF - AH_OFF));
            uint32_t bk = slotb + (uint32_t)ks2 * 16 * LDSR;
#pragma unroll
            for (int nt = 0; nt < 8; ++nt) {
                uint32_t bh[2], bl[2];
                ldsm_x2t(bh, bk + nt * 16);
                ldsm_x2t(bl, bk + nt * 16 + 8704);
                mma_bf(d[nt], ah, bh);
                mma_bf(d[nt], ah, bl);
                mma_bf(d[nt], al, bh);
            }
        }

        if (ks == 3) {
            const int cg = s >> 2;
            const float* sW0 = sWb + cg * 384;
            int r0 = row0 + wr * 16 + (lane >> 2);
            int r1 = r0 + 8;
#pragma unroll
            for (int nt = 0; nt < 8; ++nt) {
                int c = wc * 64 + nt * 8 + (lane & 3) * 2;
                float u0 = d[nt][0], u1 = d[nt][1];
                float u2 = d[nt][2], u3 = d[nt][3];
                u0 += prx[0][0] * sW0[c]     + prx[0][1] * sW0[128 + c]     + prx[0][2] * sW0[256 + c];
                u1 += prx[0][0] * sW0[c + 1] + prx[0][1] * sW0[128 + c + 1] + prx[0][2] * sW0[256 + c + 1];
                u2 += prx[1][0] * sW0[c]     + prx[1][1] * sW0[128 + c]     + prx[1][2] * sW0[256 + c];
                u3 += prx[1][0] * sW0[c + 1] + prx[1][1] * sW0[128 + c + 1] + prx[1][2] * sW0[256 + c + 1];
                if (cg == 4) {
                    u0 += sWb[1920 + c];     u0 = u0 > 0.f ? u0 : 0.2f * u0;
                    u1 += sWb[1920 + c + 1]; u1 = u1 > 0.f ? u1 : 0.2f * u1;
                    u2 += sWb[1920 + c];     u2 = u2 > 0.f ? u2 : 0.2f * u2;
                    u3 += sWb[1920 + c + 1]; u3 = u3 > 0.f ? u3 : 0.2f * u3;
                } else if (!(cg & 1)) {
                    u0 = __expf(-u0); u1 = __expf(-u1);
                    u2 = __expf(-u2); u3 = __expf(-u3);
                }
                *(float2*)(C + (size_t)r0 * ldc + cg * 128 + c) = make_float2(u0, u1);
                *(float2*)(C + (size_t)r1 * ldc + cg * 128 + c) = make_float2(u2, u3);
                d[nt][0] = 0.f; d[nt][1] = 0.f; d[nt][2] = 0.f; d[nt][3] = 0.f;
            }
        }
    }
}

// ---------------- gemm1 fused with final projection: out = T1@W2 + b2 + pos ------------
__global__ __launch_bounds__(256) void gemm1_final(
    const float* __restrict__ A,
    const __nv_bfloat16* __restrict__ Bhi, const __nv_bfloat16* __restrict__ Blo,
    const float* __restrict__ bias, const float* __restrict__ W2,
    const float* __restrict__ b2, const float* __restrict__ pos,
    float* __restrict__ out)
{
    extern __shared__ char sm[];
    __shared__ float sbias[128];
    __shared__ float sW2[384];
    __shared__ float sred[64][2][3];
    const int tid = threadIdx.x;
    const int lane = tid & 31, wid = tid >> 5;
    const int row0 = blockIdx.x * 64;
    const int NSTEP = 4;
    const uint32_t smb = smem_u32(sm);

    issue_slot(smb + RING_OFF + 0 * SLOT_SZ, Bhi, Blo, (size_t)0 * 32 * 128, tid);
    CP_COMMIT();
    issue_slot(smb + RING_OFF + 1 * SLOT_SZ, Bhi, Blo, (size_t)1 * 32 * 128, tid);
    CP_COMMIT();

    {
        int r = tid >> 2, qch = tid & 3;
        const float* Ar = A + (size_t)(row0 + r) * 128 + qch * 32;
        uint32_t* Ah = (uint32_t*)(sm + AH_OFF + r * LDSR + qch * 64);
        uint32_t* Al = (uint32_t*)(sm + AL_OFF + r * LDSR + qch * 64);
#pragma unroll
        for (int f = 0; f < 8; ++f) {
            float4 v = *(const float4*)(Ar + f * 4);
            float hx = __bfloat162float(__float2bfloat16(v.x));
            float hy = __bfloat162float(__float2bfloat16(v.y));
            float hz = __bfloat162float(__float2bfloat16(v.z));
            float hw = __bfloat162float(__float2bfloat16(v.w));
            Ah[f * 2]     = bfpack(hx, hy);
            Ah[f * 2 + 1] = bfpack(hz, hw);
            Al[f * 2]     = bfpack(v.x - hx, v.y - hy);
            Al[f * 2 + 1] = bfpack(v.z - hz, v.w - hw);
        }
    }
    if (tid < 128) sbias[tid] = bias[tid];
    for (int i = tid; i < 384; i += 256) sW2[i] = W2[i];

    const int wr = wid & 3, wc = wid >> 2;
    const uint32_t aA = smb + AH_OFF + (uint32_t)(wr * 16 + (lane & 15)) * LDSR
                      + ((lane >> 4) << 4);
    const uint32_t bBbase = smb + RING_OFF + (uint32_t)(lane & 15) * LDSR + wc * 128;

    float d[8][4];
#pragma unroll
    for (int nt = 0; nt < 8; ++nt)
#pragma unroll
        for (int q = 0; q < 4; ++q) d[nt][q] = 0.f;

#pragma unroll 1
    for (int s = 0; s < NSTEP; ++s) {
        if (s + 2 < NSTEP) {
            int sp = s + 2;
            issue_slot(smb + RING_OFF + (sp & 3) * SLOT_SZ, Bhi, Blo,
                       (size_t)sp * 32 * 128, tid);
        }
        CP_COMMIT();
        CP_WAIT2();
        __syncthreads();

        const uint32_t slotb = bBbase + (uint32_t)(s & 3) * SLOT_SZ;
#pragma unroll
        for (int ks2 = 0; ks2 < 2; ++ks2) {
            int k16 = s * 2 + ks2;
            uint32_t ah[4], al[4];
            uint32_t ak = aA + k16 * 32;
            ldsm_x4(ah, ak);
            ldsm_x4(al, ak + (AL_OFF - AH_OFF));
            uint32_t bk = slotb + (uint32_t)ks2 * 16 * LDSR;
#pragma unroll
            for (int nt = 0; nt < 8; ++nt) {
                uint32_t bh[2], bl[2];
                ldsm_x2t(bh, bk + nt * 16);
                ldsm_x2t(bl, bk + nt * 16 + 8704);
                mma_bf(d[nt], ah, bh);
                mma_bf(d[nt], ah, bl);
                mma_bf(d[nt], al, bh);
            }
        }
    }

    float s0[3] = {0.f, 0.f, 0.f}, s1[3] = {0.f, 0.f, 0.f};
#pragma unroll
    for (int nt = 0; nt < 8; ++nt) {
        int c = wc * 64 + nt * 8 + (lane & 3) * 2;
        float u0 = d[nt][0] + sbias[c];     u0 = u0 > 0.f ? u0 : 0.2f * u0;
        float u1 = d[nt][1] + sbias[c + 1]; u1 = u1 > 0.f ? u1 : 0.2f * u1;
        float u2 = d[nt][2] + sbias[c];     u2 = u2 > 0.f ? u2 : 0.2f * u2;
        float u3 = d[nt][3] + sbias[c + 1]; u3 = u3 > 0.f ? u3 : 0.2f * u3;
#pragma unroll
        for (int k = 0; k < 3; ++k) {
            s0[k] += u0 * sW2[c * 3 + k] + u1 * sW2[(c + 1) * 3 + k];
            s1[k] += u2 * sW2[c * 3 + k] + u3 * sW2[(c + 1) * 3 + k];
        }
    }
#pragma unroll
    for (int k = 0; k < 3; ++k) {
        s0[k] += __shfl_xor_sync(0xffffffffu, s0[k], 1);
        s0[k] += __shfl_xor_sync(0xffffffffu, s0[k], 2);
        s1[k] += __shfl_xor_sync(0xffffffffu, s1[k], 1);
        s1[k] += __shfl_xor_sync(0xffffffffu, s1[k], 2);
    }
    if ((lane & 3) == 0) {
        int rl0 = wr * 16 + (lane >> 2);
#pragma unroll
        for (int k = 0; k < 3; ++k) {
            sred[rl0][wc][k]     = s0[k];
            sred[rl0 + 8][wc][k] = s1[k];
        }
    }
    __syncthreads();
    if (tid < 192) {
        int r = tid / 3, k = tid - r * 3;
        int gr = row0 + r;
        out[gr * 3 + k] = sred[r][0][k] + sred[r][1][k] + b2[k] + pos[gr * 3 + k];
    }
}

// ---------------- KNN: warp-distributed sorted top-32 (exact), 8 queries/block ---------
__global__ __launch_bounds__(256) void knn_kernel(const float* __restrict__ pos) {
    __shared__ float4 p4[NN];            // 32 KB
    int tid = threadIdx.x;
    int b = blockIdx.x >> 8;             // 256 blocks per batch, 8 queries each
    int grp = blockIdx.x & 255;
    const float* pb = pos + (size_t)b * NN * 3;
    for (int j = tid; j < NN; j += 256) {
        float X = pb[j * 3], Y = pb[j * 3 + 1], Z = pb[j * 3 + 2];
        p4[j] = make_float4(X, Y, Z, X * X + Y * Y + Z * Z);
    }
    __syncthreads();
    int wid = tid >> 5, lane = tid & 31;
    int il = grp * 8 + wid;
    float4 q = p4[il];

    unsigned long long qk = 0xFFFFFFFFFFFFFFFFull;   // sorted asc across lanes

#pragma unroll 2
    for (int t = 0; t < NN / 32; ++t) {
        int j = lane + (t << 5);
        float4 pj = p4[j];
        float d2 = q.w + pj.w - 2.f * (q.x * pj.x + q.y * pj.y + q.z * pj.z);
        unsigned ub = __float_as_uint(d2);
        ub ^= ((unsigned)((int)ub >> 31)) | 0x80000000u;
        unsigned long long key = ((unsigned long long)ub << 32) | (unsigned)j;
        if (j == il) key = 0xFFFFFFFFFFFFFFFFull;
        unsigned long long kmax = __shfl_sync(0xffffffffu, qk, 31);
        unsigned surv = __ballot_sync(0xffffffffu, key < kmax);
        while (surv) {
            int src = __ffs(surv) - 1;
            surv &= surv - 1;
            unsigned long long ck = __shfl_sync(0xffffffffu, key, src);
            kmax = __shfl_sync(0xffffffffu, qk, 31);
            unsigned long long up = __shfl_up_sync(0xffffffffu, qk, 1);
            if (ck < kmax) {
                unsigned lm = __ballot_sync(0xffffffffu, qk < ck);
                int posn = __popc(lm);
                if (lane > posn)       qk = up;
                else if (lane == posn) qk = ck;
            }
        }
    }
    g_nbr[((size_t)b * NN + il) * 32 + lane] = b * NN + (int)(qk & 0xffffffffu);
}

// ---------------- neighborhood aggregation (both dilations fused) ----------------
__global__ __launch_bounds__(128) void aggregate_kernel(
    const float* __restrict__ pos, const float* __restrict__ W_pos,
    const float* __restrict__ b_pos)
{
    __shared__ float sWp[3][128];
    __shared__ float sbp[128];
    int tid = threadIdx.x;
    sbp[tid] = b_pos[tid] + b_pos[128 + tid];
#pragma unroll
    for (int r = 0; r < 3; ++r)
        sWp[r][tid] = W_pos[r * 128 + tid] + W_pos[384 + r * 128 + tid];
    __syncthreads();

    int w = tid >> 5, lane = tid & 31;
    int i = blockIdx.x * 4 + w;
    int myn = g_nbr[(size_t)i * 32 + lane];
    int c = lane << 2;

    float4 a0 = {0,0,0,0}, s0 = {0,0,0,0};
#pragma unroll
    for (int k = 0; k <= 16; ++k) {
        int j = (k < 16) ? __shfl_sync(0xffffffffu, myn, k) : i;
        const float* pr = g_P + (size_t)j * NCOLS + c;
        float4 e = *(const float4*)pr;
        float4 m = *(const float4*)(pr + 128);
        s0.x += e.x; s0.y += e.y; s0.z += e.z; s0.w += e.w;
        a0.x += e.x * m.x; a0.y += e.y * m.y; a0.z += e.z * m.z; a0.w += e.w * m.w;
    }
    float4 a1 = {0,0,0,0}, s1 = {0,0,0,0};
#pragma unroll
    for (int k = 0; k <= 16; ++k) {
        int j = (k < 16) ? __shfl_sync(0xffffffffu, myn, 2 * k) : i;
        const float* pr = g_P + (size_t)j * NCOLS + 256 + c;
        float4 e = *(const float4*)pr;
        float4 m = *(const float4*)(pr + 128);
        s1.x += e.x; s1.y += e.y; s1.z += e.z; s1.w += e.w;
        a1.x += e.x * m.x; a1.y += e.y * m.y; a1.z += e.z * m.z; a1.w += e.w * m.w;
    }

    const float* pri = g_P + (size_t)i * NCOLS;
    float4 h2 = *(const float4*)(pri + 512 + c);
    float pix = pos[i * 3], piy = pos[i * 3 + 1], piz = pos[i * 3 + 2];
    float4 outv;
    outv.x = h2.x + a0.x / s0.x + a1.x / s1.x + sbp[c + 0]
           + pix * sWp[0][c + 0] + piy * sWp[1][c + 0] + piz * sWp[2][c + 0];
    outv.y = h2.y + a0.y / s0.y + a1.y / s1.y + sbp[c + 1]
           + pix * sWp[0][c + 1] + piy * sWp[1][c + 1] + piz * sWp[2][c + 1];
    outv.z = h2.z + a0.z / s0.z + a1.z / s1.z + sbp[c + 2]
           + pix * sWp[0][c + 2] + piy * sWp[1][c + 2] + piz * sWp[2][c + 2];
    outv.w = h2.w + a0.w / s0.w + a1.w / s1.w + sbp[c + 3]
           + pix * sWp[0][c + 3] + piy * sWp[1][c + 3] + piz * sWp[2][c + 3];
    *(float4*)(g_H + (size_t)i * CC + c) = outv;
}

// ---------------- launcher ----------------
extern "C" void kernel_launch(void* const* d_in, const int* in_sizes, int n_in,
                              void* d_out, int out_size) {
    const float* x     = (const float*)d_in[0];
    const float* pos   = (const float*)d_in[1];
    const float* W_lin = (const float*)d_in[2];
    const float* W_src = (const float*)d_in[3];
    // d_in[4] = W_dst: cancels in the per-channel softmax, unused
    const float* W_pos = (const float*)d_in[5];
    const float* b_pos = (const float*)d_in[6];
    const float* Wg    = (const float*)d_in[7];
    const float* bg    = (const float*)d_in[8];
    const float* W1    = (const float*)d_in[9];
    const float* b1    = (const float*)d_in[10];
    const float* W2    = (const float*)d_in[11];
    const float* b2    = (const float*)d_in[12];
    float* out = (float*)d_out;

    cudaFuncSetAttribute(gemm_p0,     cudaFuncAttributeMaxDynamicSharedMemorySize, SMEM_DYN);
    cudaFuncSetAttribute(gemm1_final, cudaFuncAttributeMaxDynamicSharedMemorySize, SMEM_DYN);

    pack_all<<<(6 * 16384 + 5 * 384 + 255) / 256, 256>>>(W_lin, W_src, Wg, W1, W_pos);
    knn_kernel<<<NPTS / 8, 256>>>(pos);

    __nv_bfloat16 *B0h, *B0l, *B1h, *B1l;
    float *Wp3, *P, *H;
    cudaGetSymbolAddress((void**)&B0h, g_B0hi);
    cudaGetSymbolAddress((void**)&B0l, g_B0lo);
    cudaGetSymbolAddress((void**)&B1h, g_B1hi);
    cudaGetSymbolAddress((void**)&B1l, g_B1lo);
    cudaGetSymbolAddress((void**)&Wp3, g_Wp3);
    cudaGetSymbolAddress((void**)&P,   g_P);
    cudaGetSymbolAddress((void**)&H,   g_H);

    gemm_p0<<<NPTS / 64, 256, SMEM_DYN>>>(x, B0h, B0l, bg, Wp3, pos, P);
    aggregate_kernel<<<NPTS / 4, 128>>>(pos, W_pos, b_pos);
    gemm1_final<<<NPTS / 64, 256, SMEM_DYN>>>(H, B1h, B1l, b1, W2, b2, pos, out);
}